// round 13
// baseline (speedup 1.0000x reference)
#include <cuda_runtime.h>
#include <math.h>

typedef unsigned long long u64;
typedef unsigned int u32;

#define CDIM   96
#define NWIN   8192
#define TOKENS (2*64*64*64)
#define QKV_LD 292          // %32==4, 16B-aligned rows
#define S_LD   68
#define XW_LD  100          // %32==4 -> conflict-free mma A-fragment LDS
#define HB_LD  388          // %32==4

// Static device scratch (no allocs allowed)
__device__ float g_scratch[(size_t)TOKENS * CDIM];
// Fragment-packed tf32 weights (u64 = {b0 lo, b1 hi})
__device__ u64 g_wqkvf[2 * 12 * 36 * 32];   // K=96 (KT12), N=288 (NT36)
__device__ u64 g_w1f  [2 * 12 * 48 * 32];   // K=96,  N=384
__device__ u64 g_w2f  [2 * 48 * 12 * 32];   // K=384, N=96
__device__ u64 g_wpf  [2 * 12 * 12 * 32];   // K=96,  N=96 (proj)
// Dense rel-pos bias: [layer][head][q=64][k=64]
__device__ float g_bias[2 * 3 * 64 * 64];

#define ASMEM ((64*XW_LD + 64*QKV_LD + 3*64*S_LD) * 4)
#define MSMEM ((64*XW_LD + 64*HB_LD) * 4)

// ---- tf32 helpers ----
__device__ __forceinline__ u32 tf32bits(float x) {
    u32 r; asm("cvt.rna.tf32.f32 %0,%1;" : "=r"(r) : "f"(x)); return r;
}
__device__ __forceinline__ float tf32r(float x) {
    return __uint_as_float(tf32bits(x));
}
__device__ __forceinline__ void mma_tf32(
    float& c0, float& c1, float& c2, float& c3,
    u32 a0, u32 a1, u32 a2, u32 a3, u32 b0, u32 b1)
{
    asm("mma.sync.aligned.m16n8k8.row.col.f32.tf32.tf32.f32 "
        "{%0,%1,%2,%3},{%4,%5,%6,%7},{%8,%9},{%0,%1,%2,%3};"
        : "+f"(c0), "+f"(c1), "+f"(c2), "+f"(c3)
        : "r"(a0), "r"(a1), "r"(a2), "r"(a3), "r"(b0), "r"(b1));
}

// ---------------------------------------------------------------------------
// Pack row-major W[K][N] (per layer) into mma B-fragment order.
// ---------------------------------------------------------------------------
__global__ void pack_kernel(const float* __restrict__ W, u64* __restrict__ dst,
                            int KT, int NT, int N, int total)
{
    int i = blockIdx.x * blockDim.x + threadIdx.x;
    if (i >= total) return;
    int per_layer = KT * NT * 32;
    int layer = i / per_layer;
    int r = i - layer * per_layer;
    int t = r >> 5, lane = r & 31;
    int kt = t / NT, nt = t - kt * NT;
    int k = kt * 8 + (lane & 3);
    int n = nt * 8 + (lane >> 2);
    const float* Wl = W + (size_t)layer * (KT * 8) * N;
    u32 lo = tf32bits(Wl[(size_t)k * N + n]);
    u32 hi = tf32bits(Wl[(size_t)(k + 4) * N + n]);
    dst[i] = ((u64)hi << 32) | lo;
}

// ---------------------------------------------------------------------------
// Precompute dense rel-pos bias matrices (window-invariant).
// ---------------------------------------------------------------------------
__global__ void bias_kernel(const float* __restrict__ tb) {
    int i = blockIdx.x * blockDim.x + threadIdx.x;
    if (i >= 2*3*64*64) return;
    int layer = i / (3*4096);
    int r = i % (3*4096);
    int h = r / 4096;
    int qk = r & 4095;
    int q = qk >> 6, k = qk & 63;
    int qd = q >> 4, qh = (q >> 2) & 3, qw = q & 3;
    int kd = k >> 4, kh = (k >> 2) & 3, kw = k & 3;
    int ridx = (qd-kd+3)*49 + (qh-kh+3)*7 + (qw-kw+3);
    g_bias[i] = tb[layer*1029 + ridx*3 + h];
}

// ---------------------------------------------------------------------------
// Attention block, all GEMMs on tensor cores.
// One CTA per 4x4x4 window, 512 threads (16 warps: mt=warp&3, ng=warp>>2).
// ---------------------------------------------------------------------------
__global__ __launch_bounds__(512, 1) void attn_kernel(
    const float* __restrict__ x, float* __restrict__ out,
    const u64*  __restrict__ Wqkvf, const float* __restrict__ Bqkv,
    const u64*  __restrict__ Wpf,   const float* __restrict__ Bp,
    const float* __restrict__ biasM,
    const float* __restrict__ g1,   const float* __restrict__ b1,
    int shift)
{
    extern __shared__ float sm[];
    float* xw  = sm;                    // 64 x XW_LD; later aliased as ao
    float* qkv = xw + 64*XW_LD;         // 64 x 292 (tf32-rounded)
    float* S3  = qkv + 64*QKV_LD;       // 3 x 64 x 68
    float* ao  = xw;

    const int tid  = threadIdx.x;
    const int lane = tid & 31;
    const int warp = tid >> 5;
    const int mt   = warp & 3;
    const int ng   = warp >> 2;
    const int gid  = lane >> 2;
    const int tig  = lane & 3;

    const int bw   = blockIdx.x;
    const int b    = bw >> 12;
    const int widx = bw & 4095;
    const int wd   = widx >> 8;
    const int wh   = (widx >> 4) & 15;
    const int ww   = widx & 15;

    // ---- LN1 (one warp per token), store tf32-rounded ----
    for (int t = warp; t < 64; t += 16) {
        int td = t >> 4, th = (t >> 2) & 3, tw = t & 3;
        int gd = (wd*4 + td + shift) & 63;
        int gh = (wh*4 + th + shift) & 63;
        int gw = (ww*4 + tw + shift) & 63;
        const float* src = x + (size_t)((((b*64 + gd)*64 + gh)*64 + gw)) * 96;
        float v0 = src[lane], v1 = src[lane+32], v2 = src[lane+64];
        float s  = v0 + v1 + v2;
        float sq = v0*v0 + v1*v1 + v2*v2;
        #pragma unroll
        for (int o = 16; o; o >>= 1) {
            s  += __shfl_xor_sync(0xffffffffu, s,  o);
            sq += __shfl_xor_sync(0xffffffffu, sq, o);
        }
        float mean = s * (1.0f/96.0f);
        float var  = sq * (1.0f/96.0f) - mean*mean;
        float rstd = rsqrtf(var + 1e-5f);
        xw[t*XW_LD+lane]    = tf32r((v0-mean)*rstd*g1[lane]    + b1[lane]);
        xw[t*XW_LD+lane+32] = tf32r((v1-mean)*rstd*g1[lane+32] + b1[lane+32]);
        xw[t*XW_LD+lane+64] = tf32r((v2-mean)*rstd*g1[lane+64] + b1[lane+64]);
    }
    __syncthreads();

    // ---- QKV GEMM (MMA): 9 n-tiles per warp; outputs tf32-rounded, q scaled ----
    {
        float acc[9][4];
        #pragma unroll
        for (int nt = 0; nt < 9; nt++) {
            int col0 = 72*ng + 8*nt + 2*tig;
            float2 bb = *(const float2*)&Bqkv[col0];
            acc[nt][0] = bb.x; acc[nt][1] = bb.y;
            acc[nt][2] = bb.x; acc[nt][3] = bb.y;
        }
        #pragma unroll
        for (int kt = 0; kt < 12; kt++) {
            const float* arow0 = &xw[(16*mt + gid)*XW_LD + 8*kt];
            const float* arow1 = arow0 + 8*XW_LD;
            u32 a0 = __float_as_uint(arow0[tig]);
            u32 a1 = __float_as_uint(arow1[tig]);
            u32 a2 = __float_as_uint(arow0[tig+4]);
            u32 a3 = __float_as_uint(arow1[tig+4]);
            #pragma unroll
            for (int nt = 0; nt < 9; nt++) {
                u64 w = Wqkvf[(kt*36 + ng*9 + nt)*32 + lane];
                mma_tf32(acc[nt][0], acc[nt][1], acc[nt][2], acc[nt][3],
                         a0, a1, a2, a3, (u32)w, (u32)(w >> 32));
            }
        }
        const float qs = 0.17677669529663687f;  // 32^-0.5
        #pragma unroll
        for (int nt = 0; nt < 9; nt++) {
            int col0 = 72*ng + 8*nt + 2*tig;
            float sc = (72*ng + 8*nt < 96) ? qs : 1.0f;
            *(float2*)&qkv[(16*mt + gid)*QKV_LD + col0] =
                make_float2(tf32r(acc[nt][0]*sc), tf32r(acc[nt][1]*sc));
            *(float2*)&qkv[(16*mt + gid + 8)*QKV_LD + col0] =
                make_float2(tf32r(acc[nt][2]*sc), tf32r(acc[nt][3]*sc));
        }
    }
    __syncthreads();

    // ---- S = qK^T + bias (MMA): per head, ng covers 16 cols (2 n-tiles) ----
    #pragma unroll
    for (int h = 0; h < 3; h++) {
        float acc[2][4];
        #pragma unroll
        for (int j = 0; j < 2; j++)
            acc[j][0] = acc[j][1] = acc[j][2] = acc[j][3] = 0.f;
        #pragma unroll
        for (int ks = 0; ks < 4; ks++) {
            const float* ap = &qkv[(16*mt + gid)*QKV_LD + h*32 + 8*ks];
            u32 a0 = __float_as_uint(ap[tig]);
            u32 a1 = __float_as_uint(ap[8*QKV_LD + tig]);
            u32 a2 = __float_as_uint(ap[tig+4]);
            u32 a3 = __float_as_uint(ap[8*QKV_LD + tig+4]);
            #pragma unroll
            for (int j = 0; j < 2; j++) {
                const float* bp = &qkv[(ng*16 + j*8 + gid)*QKV_LD + 96 + h*32 + 8*ks];
                u32 b0 = __float_as_uint(bp[tig]);
                u32 b1 = __float_as_uint(bp[tig+4]);
                mma_tf32(acc[j][0], acc[j][1], acc[j][2], acc[j][3],
                         a0, a1, a2, a3, b0, b1);
            }
        }
        const float* bh = biasM + h*4096;
        #pragma unroll
        for (int j = 0; j < 2; j++) {
            int col = ng*16 + j*8 + 2*tig;
            int q0  = 16*mt + gid;
            float2 bb0 = *(const float2*)&bh[q0*64 + col];
            float2 bb1 = *(const float2*)&bh[(q0+8)*64 + col];
            *(float2*)&S3[(h*64 + q0)*S_LD + col] =
                make_float2(acc[j][0] + bb0.x, acc[j][1] + bb0.y);
            *(float2*)&S3[(h*64 + q0 + 8)*S_LD + col] =
                make_float2(acc[j][2] + bb1.x, acc[j][3] + bb1.y);
        }
    }
    __syncthreads();

    // ---- softmax: 8 lanes per row, all heads; probs tf32-rounded ----
    {
        int row = tid >> 3, sub = tid & 7;
        #pragma unroll
        for (int h = 0; h < 3; h++) {
            float* Sr = &S3[(h*64 + row)*S_LD + sub*8];
            float4 v0 = *(float4*)Sr;
            float4 v1 = *(float4*)(Sr + 4);
            float vals[8] = {v0.x,v0.y,v0.z,v0.w, v1.x,v1.y,v1.z,v1.w};
            float m = vals[0];
            #pragma unroll
            for (int c = 1; c < 8; c++) m = fmaxf(m, vals[c]);
            m = fmaxf(m, __shfl_xor_sync(0xffffffffu, m, 1));
            m = fmaxf(m, __shfl_xor_sync(0xffffffffu, m, 2));
            m = fmaxf(m, __shfl_xor_sync(0xffffffffu, m, 4));
            float ssum = 0.f;
            #pragma unroll
            for (int c = 0; c < 8; c++) { vals[c] = __expf(vals[c] - m); ssum += vals[c]; }
            ssum += __shfl_xor_sync(0xffffffffu, ssum, 1);
            ssum += __shfl_xor_sync(0xffffffffu, ssum, 2);
            ssum += __shfl_xor_sync(0xffffffffu, ssum, 4);
            float inv = 1.0f / ssum;
            *(float4*)Sr = make_float4(tf32r(vals[0]*inv), tf32r(vals[1]*inv),
                                       tf32r(vals[2]*inv), tf32r(vals[3]*inv));
            *(float4*)(Sr+4) = make_float4(tf32r(vals[4]*inv), tf32r(vals[5]*inv),
                                           tf32r(vals[6]*inv), tf32r(vals[7]*inv));
        }
    }
    __syncthreads();

    // ---- P@V (MMA): output 64x96, ng covers 24 cols (3 n-tiles) ----
    {
        float acc[3][4];
        #pragma unroll
        for (int j = 0; j < 3; j++)
            acc[j][0] = acc[j][1] = acc[j][2] = acc[j][3] = 0.f;
        #pragma unroll
        for (int j = 0; j < 3; j++) {
            int ct = ng*24 + j*8;
            int h  = ct >> 5;
            int dc = ct & 31;
            #pragma unroll
            for (int ks = 0; ks < 8; ks++) {
                const float* ap = &S3[(h*64 + 16*mt + gid)*S_LD + 8*ks];
                u32 a0 = __float_as_uint(ap[tig]);
                u32 a1 = __float_as_uint(ap[8*S_LD + tig]);
                u32 a2 = __float_as_uint(ap[tig+4]);
                u32 a3 = __float_as_uint(ap[8*S_LD + tig+4]);
                const float* bp = &qkv[(8*ks + tig)*QKV_LD + 192 + h*32 + dc + gid];
                u32 b0 = __float_as_uint(bp[0]);
                u32 b1 = __float_as_uint(bp[4*QKV_LD]);
                mma_tf32(acc[j][0], acc[j][1], acc[j][2], acc[j][3],
                         a0, a1, a2, a3, b0, b1);
            }
        }
        __syncthreads();   // xw/ao alias: ensure no one still needs xw (dead) / ordering
        #pragma unroll
        for (int j = 0; j < 3; j++) {
            int ct = ng*24 + j*8 + 2*tig;
            *(float2*)&ao[(16*mt + gid)*XW_LD + ct] =
                make_float2(tf32r(acc[j][0]), tf32r(acc[j][1]));
            *(float2*)&ao[(16*mt + gid + 8)*XW_LD + ct] =
                make_float2(tf32r(acc[j][2]), tf32r(acc[j][3]));
        }
    }
    __syncthreads();

    // ---- proj (MMA) + bias + residual -> global (shifted) ----
    {
        float acc[3][4];
        #pragma unroll
        for (int j = 0; j < 3; j++)
            acc[j][0] = acc[j][1] = acc[j][2] = acc[j][3] = 0.f;
        #pragma unroll
        for (int kt = 0; kt < 12; kt++) {
            const float* ap = &ao[(16*mt + gid)*XW_LD + 8*kt];
            u32 a0 = __float_as_uint(ap[tig]);
            u32 a1 = __float_as_uint(ap[8*XW_LD + tig]);
            u32 a2 = __float_as_uint(ap[tig+4]);
            u32 a3 = __float_as_uint(ap[8*XW_LD + tig+4]);
            #pragma unroll
            for (int j = 0; j < 3; j++) {
                u64 w = Wpf[(kt*12 + ng*3 + j)*32 + lane];
                mma_tf32(acc[j][0], acc[j][1], acc[j][2], acc[j][3],
                         a0, a1, a2, a3, (u32)w, (u32)(w >> 32));
            }
        }
        // epilogue: two rows per fragment
        int q0 = 16*mt + gid;
        #pragma unroll
        for (int rr = 0; rr < 2; rr++) {
            int t = q0 + 8*rr;
            int td = t >> 4, th = (t >> 2) & 3, tw = t & 3;
            int gd = (wd*4 + td + shift) & 63;
            int gh = (wh*4 + th + shift) & 63;
            int gw = (ww*4 + tw + shift) & 63;
            size_t idx = (size_t)((((b*64 + gd)*64 + gh)*64 + gw)) * 96;
            const float* rx = x + idx;
            float* dst = out + idx;
            #pragma unroll
            for (int j = 0; j < 3; j++) {
                int ct = ng*24 + j*8 + 2*tig;
                float2 bb = *(const float2*)&Bp[ct];
                float2 rv = *(const float2*)&rx[ct];
                *(float2*)&dst[ct] = make_float2(
                    acc[j][2*rr]   + bb.x + rv.x,
                    acc[j][2*rr+1] + bb.y + rv.y);
            }
        }
    }
}

// ---------------------------------------------------------------------------
// MLP block (unchanged from R7): LN2 -> GEMM1(MMA) -> GELU -> GEMM2(MMA)
// ---------------------------------------------------------------------------
__global__ __launch_bounds__(512, 1) void mlp_kernel(
    float* __restrict__ xa,
    const float* __restrict__ g2, const float* __restrict__ b2ln,
    const u64*  __restrict__ W1f, const float* __restrict__ B1,
    const u64*  __restrict__ W2f, const float* __restrict__ B2)
{
    extern __shared__ float sm[];
    float* y  = sm;             // 64 x XW_LD
    float* hb = y + 64*XW_LD;   // 64 x HB_LD

    const int tid  = threadIdx.x;
    const int lane = tid & 31;
    const int warp = tid >> 5;
    const size_t base = (size_t)blockIdx.x * 64;

    const int mt = warp & 3, ng = warp >> 2;
    const int gid = lane >> 2, tig = lane & 3;

    for (int t = warp; t < 64; t += 16) {
        const float* src = xa + (base + t) * 96;
        float v0 = src[lane], v1 = src[lane+32], v2 = src[lane+64];
        float s  = v0 + v1 + v2;
        float sq = v0*v0 + v1*v1 + v2*v2;
        #pragma unroll
        for (int o = 16; o; o >>= 1) {
            s  += __shfl_xor_sync(0xffffffffu, s,  o);
            sq += __shfl_xor_sync(0xffffffffu, sq, o);
        }
        float mean = s * (1.0f/96.0f);
        float var  = sq * (1.0f/96.0f) - mean*mean;
        float rstd = rsqrtf(var + 1e-5f);
        y[t*XW_LD+lane]    = tf32r((v0-mean)*rstd*g2[lane]    + b2ln[lane]);
        y[t*XW_LD+lane+32] = tf32r((v1-mean)*rstd*g2[lane+32] + b2ln[lane+32]);
        y[t*XW_LD+lane+64] = tf32r((v2-mean)*rstd*g2[lane+64] + b2ln[lane+64]);
    }
    __syncthreads();

    {
        float acc[12][4];
        #pragma unroll
        for (int nt = 0; nt < 12; nt++)
            acc[nt][0] = acc[nt][1] = acc[nt][2] = acc[nt][3] = 0.f;
        #pragma unroll
        for (int kt = 0; kt < 12; kt++) {
            const float* arow0 = &y[(16*mt + gid)*XW_LD + 8*kt];
            const float* arow1 = arow0 + 8*XW_LD;
            u32 a0 = __float_as_uint(arow0[tig]);
            u32 a1 = __float_as_uint(arow1[tig]);
            u32 a2 = __float_as_uint(arow0[tig+4]);
            u32 a3 = __float_as_uint(arow1[tig+4]);
            #pragma unroll
            for (int nt = 0; nt < 12; nt++) {
                u64 w = W1f[(kt*48 + ng*12 + nt)*32 + lane];
                mma_tf32(acc[nt][0], acc[nt][1], acc[nt][2], acc[nt][3],
                         a0, a1, a2, a3, (u32)w, (u32)(w >> 32));
            }
        }
        #pragma unroll
        for (int nt = 0; nt < 12; nt++) {
            int col0 = 96*ng + 8*nt + 2*tig;
            float2 bb = *(const float2*)&B1[col0];
            float u0 = acc[nt][0] + bb.x, u1 = acc[nt][1] + bb.y;
            float u2 = acc[nt][2] + bb.x, u3 = acc[nt][3] + bb.y;
            float g0 = 0.5f*u0*(1.0f + erff(u0*0.70710678118654752f));
            float g1v= 0.5f*u1*(1.0f + erff(u1*0.70710678118654752f));
            float g2v= 0.5f*u2*(1.0f + erff(u2*0.70710678118654752f));
            float g3 = 0.5f*u3*(1.0f + erff(u3*0.70710678118654752f));
            *(float2*)&hb[(16*mt + gid)*HB_LD + col0]     = make_float2(tf32r(g0), tf32r(g1v));
            *(float2*)&hb[(16*mt + gid + 8)*HB_LD + col0] = make_float2(tf32r(g2v), tf32r(g3));
        }
    }
    __syncthreads();

    {
        float acc[3][4];
        #pragma unroll
        for (int nt = 0; nt < 3; nt++)
            acc[nt][0] = acc[nt][1] = acc[nt][2] = acc[nt][3] = 0.f;
        #pragma unroll
        for (int kt = 0; kt < 48; kt++) {
            const float* arow0 = &hb[(16*mt + gid)*HB_LD + 8*kt];
            const float* arow1 = arow0 + 8*HB_LD;
            u32 a0 = __float_as_uint(arow0[tig]);
            u32 a1 = __float_as_uint(arow1[tig]);
            u32 a2 = __float_as_uint(arow0[tig+4]);
            u32 a3 = __float_as_uint(arow1[tig+4]);
            #pragma unroll
            for (int nt = 0; nt < 3; nt++) {
                u64 w = W2f[(kt*12 + ng*3 + nt)*32 + lane];
                mma_tf32(acc[nt][0], acc[nt][1], acc[nt][2], acc[nt][3],
                         a0, a1, a2, a3, (u32)w, (u32)(w >> 32));
            }
        }
        #pragma unroll
        for (int nt = 0; nt < 3; nt++) {
            int col0 = 24*ng + 8*nt + 2*tig;
            float2 bb = *(const float2*)&B2[col0];
            float* p0 = xa + (base + 16*mt + gid) * 96 + col0;
            float* p1 = xa + (base + 16*mt + gid + 8) * 96 + col0;
            float2 r0 = *(float2*)p0;
            float2 r1 = *(float2*)p1;
            *(float2*)p0 = make_float2(acc[nt][0] + bb.x + r0.x, acc[nt][1] + bb.y + r0.y);
            *(float2*)p1 = make_float2(acc[nt][2] + bb.x + r1.x, acc[nt][3] + bb.y + r1.y);
        }
    }
}

// ---------------------------------------------------------------------------
extern "C" void kernel_launch(void* const* d_in, const int* in_sizes, int n_in,
                              void* d_out, int out_size)
{
    const float* x      = (const float*)d_in[0];
    const float* qkv_w  = (const float*)d_in[1];
    const float* qkv_b  = (const float*)d_in[2];
    const float* proj_w = (const float*)d_in[3];
    const float* proj_b = (const float*)d_in[4];
    const float* btab   = (const float*)d_in[5];
    const float* ln1g   = (const float*)d_in[6];
    const float* ln1b   = (const float*)d_in[7];
    const float* ln2g   = (const float*)d_in[8];
    const float* ln2b   = (const float*)d_in[9];
    const float* w1     = (const float*)d_in[10];
    const float* b1     = (const float*)d_in[11];
    const float* w2     = (const float*)d_in[12];
    const float* b2     = (const float*)d_in[13];
    float* out = (float*)d_out;

    float* scratch = nullptr;
    u64 *wqkvf = nullptr, *w1f = nullptr, *w2f = nullptr, *wpf = nullptr;
    float* biasm = nullptr;
    cudaGetSymbolAddress((void**)&scratch, g_scratch);
    cudaGetSymbolAddress((void**)&wqkvf,   g_wqkvf);
    cudaGetSymbolAddress((void**)&w1f,     g_w1f);
    cudaGetSymbolAddress((void**)&w2f,     g_w2f);
    cudaGetSymbolAddress((void**)&wpf,     g_wpf);
    cudaGetSymbolAddress((void**)&biasm,   g_bias);

    cudaFuncSetAttribute(attn_kernel, cudaFuncAttributeMaxDynamicSharedMemorySize, ASMEM);
    cudaFuncSetAttribute(mlp_kernel,  cudaFuncAttributeMaxDynamicSharedMemorySize, MSMEM);

    // Prep: fragment-pack weights + dense bias matrices
    {
        int tq = 2*12*36*32, t1 = 2*12*48*32, t2 = 2*48*12*32, tp = 2*12*12*32;
        pack_kernel<<<(tq+255)/256, 256>>>(qkv_w, wqkvf, 12, 36, 288, tq);
        pack_kernel<<<(t1+255)/256, 256>>>(w1,    w1f,   12, 48, 384, t1);
        pack_kernel<<<(t2+255)/256, 256>>>(w2,    w2f,   48, 12,  96, t2);
        pack_kernel<<<(tp+255)/256, 256>>>(proj_w, wpf,  12, 12,  96, tp);
        bias_kernel<<<(2*3*64*64+255)/256, 256>>>(btab);
    }

    // ---- block 0 (shift 0) ----
    attn_kernel<<<NWIN, 512, ASMEM>>>(x, scratch,
        wqkvf, qkv_b, wpf, proj_b, biasm, ln1g, ln1b, 0);
    mlp_kernel<<<TOKENS/64, 512, MSMEM>>>(scratch,
        ln2g, ln2b, w1f, b1, w2f, b2);

    // ---- block 1 (shift 2) ----
    attn_kernel<<<NWIN, 512, ASMEM>>>(scratch, out,
        wqkvf + 12*36*32, qkv_b + 288, wpf + 12*12*32, proj_b + 96,
        biasm + 3*64*64, ln1g + 96, ln1b + 96, 2);
    mlp_kernel<<<TOKENS/64, 512, MSMEM>>>(out,
        ln2g + 96, ln2b + 96, w1f + 12*48*32, b1 + 384, w2f + 48*12*32, b2 + 96);
}

// round 14
// speedup vs baseline: 1.0585x; 1.0585x over previous
#include <cuda_runtime.h>
#include <math.h>

typedef unsigned long long u64;
typedef unsigned int u32;

#define CDIM   96
#define NWIN   8192
#define TOKENS (2*64*64*64)
#define QKV_LD 292          // %32==4, 16B-aligned rows
#define S_LD   68
#define XW_LD  100          // %32==4 -> conflict-free mma A-fragment LDS
#define HB_LD  388          // %32==4

// Static device scratch (no allocs allowed)
__device__ float g_scratch[(size_t)TOKENS * CDIM];
// Fragment-packed tf32 weights (u64 = {b0 lo, b1 hi})
__device__ u64 g_wqkvf[2 * 12 * 36 * 32];   // K=96 (KT12), N=288 (NT36)
__device__ u64 g_w1f  [2 * 12 * 48 * 32];   // K=96,  N=384
__device__ u64 g_w2f  [2 * 48 * 12 * 32];   // K=384, N=96
__device__ u64 g_wpf  [2 * 12 * 12 * 32];   // K=96,  N=96 (proj)
// Dense rel-pos bias: [layer][head][q=64][k=64]
__device__ float g_bias[2 * 3 * 64 * 64];

// Fused-kernel smem: xres(6144) + xw(6400) + qkv(18688) + S3(13056)
#define FSMEM ((64*96 + 64*XW_LD + 64*QKV_LD + 3*64*S_LD) * 4)

// ---- tf32 helpers ----
__device__ __forceinline__ u32 tf32bits(float x) {
    u32 r; asm("cvt.rna.tf32.f32 %0,%1;" : "=r"(r) : "f"(x)); return r;
}
__device__ __forceinline__ float tf32r(float x) {
    return __uint_as_float(tf32bits(x));
}
__device__ __forceinline__ void mma_tf32(
    float& c0, float& c1, float& c2, float& c3,
    u32 a0, u32 a1, u32 a2, u32 a3, u32 b0, u32 b1)
{
    asm("mma.sync.aligned.m16n8k8.row.col.f32.tf32.tf32.f32 "
        "{%0,%1,%2,%3},{%4,%5,%6,%7},{%8,%9},{%0,%1,%2,%3};"
        : "+f"(c0), "+f"(c1), "+f"(c2), "+f"(c3)
        : "r"(a0), "r"(a1), "r"(a2), "r"(a3), "r"(b0), "r"(b1));
}

// ---------------------------------------------------------------------------
// Pack row-major W[K][N] (per layer) into mma B-fragment order.
// ---------------------------------------------------------------------------
__global__ void pack_kernel(const float* __restrict__ W, u64* __restrict__ dst,
                            int KT, int NT, int N, int total)
{
    int i = blockIdx.x * blockDim.x + threadIdx.x;
    if (i >= total) return;
    int per_layer = KT * NT * 32;
    int layer = i / per_layer;
    int r = i - layer * per_layer;
    int t = r >> 5, lane = r & 31;
    int kt = t / NT, nt = t - kt * NT;
    int k = kt * 8 + (lane & 3);
    int n = nt * 8 + (lane >> 2);
    const float* Wl = W + (size_t)layer * (KT * 8) * N;
    u32 lo = tf32bits(Wl[(size_t)k * N + n]);
    u32 hi = tf32bits(Wl[(size_t)(k + 4) * N + n]);
    dst[i] = ((u64)hi << 32) | lo;
}

// ---------------------------------------------------------------------------
// Precompute dense rel-pos bias matrices (window-invariant).
// ---------------------------------------------------------------------------
__global__ void bias_kernel(const float* __restrict__ tb) {
    int i = blockIdx.x * blockDim.x + threadIdx.x;
    if (i >= 2*3*64*64) return;
    int layer = i / (3*4096);
    int r = i % (3*4096);
    int h = r / 4096;
    int qk = r & 4095;
    int q = qk >> 6, k = qk & 63;
    int qd = q >> 4, qh = (q >> 2) & 3, qw = q & 3;
    int kd = k >> 4, kh = (k >> 2) & 3, kw = k & 3;
    int ridx = (qd-kd+3)*49 + (qh-kh+3)*7 + (qw-kw+3);
    g_bias[i] = tb[layer*1029 + ridx*3 + h];
}

// ---------------------------------------------------------------------------
// Fully fused Swin block: LN1 -> QKV -> S(+bias) -> softmax -> P@V -> proj
// -> +residual (smem) -> LN2 -> MLP(GEMM1+GELU+GEMM2) -> +residual -> out.
// One CTA per 4x4x4 window, 512 threads (16 warps: mt=warp&3, ng=warp>>2).
// Reads x once, writes out once.
// ---------------------------------------------------------------------------
__global__ __launch_bounds__(512, 1) void block_kernel(
    const float* __restrict__ x, float* __restrict__ out,
    const u64*  __restrict__ Wqkvf, const float* __restrict__ Bqkv,
    const u64*  __restrict__ Wpf,   const float* __restrict__ Bp,
    const float* __restrict__ biasM,
    const float* __restrict__ g1,   const float* __restrict__ b1,
    const float* __restrict__ g2,   const float* __restrict__ b2ln,
    const u64*  __restrict__ W1f,   const float* __restrict__ B1,
    const u64*  __restrict__ W2f,   const float* __restrict__ B2,
    int shift)
{
    extern __shared__ float sm[];
    float* xres = sm;                    // 64 x 96: raw x, later x+attn (residual)
    float* xw   = xres + 64*96;          // 64 x XW_LD: LN1 out; aliased ao, then y
    float* qkv  = xw + 64*XW_LD;         // 64 x 292 (tf32-rounded)
    float* S3   = qkv + 64*QKV_LD;       // 3 x 64 x 68
    float* ao   = xw;
    float* y    = xw;
    float* hb   = qkv;                   // 64 x HB_LD aliases qkv+S3 (dead by then)

    const int tid  = threadIdx.x;
    const int lane = tid & 31;
    const int warp = tid >> 5;
    const int mt   = warp & 3;
    const int ng   = warp >> 2;
    const int gid  = lane >> 2;
    const int tig  = lane & 3;

    const int bw   = blockIdx.x;
    const int b    = bw >> 12;
    const int widx = bw & 4095;
    const int wd   = widx >> 8;
    const int wh   = (widx >> 4) & 15;
    const int ww   = widx & 15;

    // ---- Phase 1: load x (shifted) + LN1; keep raw x in xres ----
    for (int t = warp; t < 64; t += 16) {
        int td = t >> 4, th = (t >> 2) & 3, tw = t & 3;
        int gd = (wd*4 + td + shift) & 63;
        int gh = (wh*4 + th + shift) & 63;
        int gw = (ww*4 + tw + shift) & 63;
        const float* src = x + (size_t)((((b*64 + gd)*64 + gh)*64 + gw)) * 96;
        float v0 = src[lane], v1 = src[lane+32], v2 = src[lane+64];
        float s  = v0 + v1 + v2;
        float sq = v0*v0 + v1*v1 + v2*v2;
        #pragma unroll
        for (int o = 16; o; o >>= 1) {
            s  += __shfl_xor_sync(0xffffffffu, s,  o);
            sq += __shfl_xor_sync(0xffffffffu, sq, o);
        }
        float mean = s * (1.0f/96.0f);
        float var  = sq * (1.0f/96.0f) - mean*mean;
        float rstd = rsqrtf(var + 1e-5f);
        xres[t*96+lane]    = v0;
        xres[t*96+lane+32] = v1;
        xres[t*96+lane+64] = v2;
        xw[t*XW_LD+lane]    = tf32r((v0-mean)*rstd*g1[lane]    + b1[lane]);
        xw[t*XW_LD+lane+32] = tf32r((v1-mean)*rstd*g1[lane+32] + b1[lane+32]);
        xw[t*XW_LD+lane+64] = tf32r((v2-mean)*rstd*g1[lane+64] + b1[lane+64]);
    }
    __syncthreads();

    // ---- Phase 2: QKV GEMM (MMA), 9 n-tiles/warp; q pre-scaled, tf32-rounded ----
    {
        float acc[9][4];
        #pragma unroll
        for (int nt = 0; nt < 9; nt++) {
            int col0 = 72*ng + 8*nt + 2*tig;
            float2 bb = *(const float2*)&Bqkv[col0];
            acc[nt][0] = bb.x; acc[nt][1] = bb.y;
            acc[nt][2] = bb.x; acc[nt][3] = bb.y;
        }
        #pragma unroll
        for (int kt = 0; kt < 12; kt++) {
            const float* arow0 = &xw[(16*mt + gid)*XW_LD + 8*kt];
            const float* arow1 = arow0 + 8*XW_LD;
            u32 a0 = __float_as_uint(arow0[tig]);
            u32 a1 = __float_as_uint(arow1[tig]);
            u32 a2 = __float_as_uint(arow0[tig+4]);
            u32 a3 = __float_as_uint(arow1[tig+4]);
            #pragma unroll
            for (int nt = 0; nt < 9; nt++) {
                u64 w = Wqkvf[(kt*36 + ng*9 + nt)*32 + lane];
                mma_tf32(acc[nt][0], acc[nt][1], acc[nt][2], acc[nt][3],
                         a0, a1, a2, a3, (u32)w, (u32)(w >> 32));
            }
        }
        const float qs = 0.17677669529663687f;  // 32^-0.5
        #pragma unroll
        for (int nt = 0; nt < 9; nt++) {
            int col0 = 72*ng + 8*nt + 2*tig;
            float sc = (72*ng + 8*nt < 96) ? qs : 1.0f;
            *(float2*)&qkv[(16*mt + gid)*QKV_LD + col0] =
                make_float2(tf32r(acc[nt][0]*sc), tf32r(acc[nt][1]*sc));
            *(float2*)&qkv[(16*mt + gid + 8)*QKV_LD + col0] =
                make_float2(tf32r(acc[nt][2]*sc), tf32r(acc[nt][3]*sc));
        }
    }
    __syncthreads();

    // ---- Phase 3: S = qK^T + bias (MMA), per head ng covers 16 cols ----
    #pragma unroll
    for (int h = 0; h < 3; h++) {
        float acc[2][4];
        #pragma unroll
        for (int j = 0; j < 2; j++)
            acc[j][0] = acc[j][1] = acc[j][2] = acc[j][3] = 0.f;
        #pragma unroll
        for (int ks = 0; ks < 4; ks++) {
            const float* ap = &qkv[(16*mt + gid)*QKV_LD + h*32 + 8*ks];
            u32 a0 = __float_as_uint(ap[tig]);
            u32 a1 = __float_as_uint(ap[8*QKV_LD + tig]);
            u32 a2 = __float_as_uint(ap[tig+4]);
            u32 a3 = __float_as_uint(ap[8*QKV_LD + tig+4]);
            #pragma unroll
            for (int j = 0; j < 2; j++) {
                const float* bp = &qkv[(ng*16 + j*8 + gid)*QKV_LD + 96 + h*32 + 8*ks];
                u32 b0 = __float_as_uint(bp[tig]);
                u32 b1 = __float_as_uint(bp[tig+4]);
                mma_tf32(acc[j][0], acc[j][1], acc[j][2], acc[j][3],
                         a0, a1, a2, a3, b0, b1);
            }
        }
        const float* bh = biasM + h*4096;
        #pragma unroll
        for (int j = 0; j < 2; j++) {
            int col = ng*16 + j*8 + 2*tig;
            int q0  = 16*mt + gid;
            float2 bb0 = *(const float2*)&bh[q0*64 + col];
            float2 bb1 = *(const float2*)&bh[(q0+8)*64 + col];
            *(float2*)&S3[(h*64 + q0)*S_LD + col] =
                make_float2(acc[j][0] + bb0.x, acc[j][1] + bb0.y);
            *(float2*)&S3[(h*64 + q0 + 8)*S_LD + col] =
                make_float2(acc[j][2] + bb1.x, acc[j][3] + bb1.y);
        }
    }
    __syncthreads();

    // ---- Phase 4: softmax (8 lanes/row), probs tf32-rounded ----
    {
        int row = tid >> 3, sub = tid & 7;
        #pragma unroll
        for (int h = 0; h < 3; h++) {
            float* Sr = &S3[(h*64 + row)*S_LD + sub*8];
            float4 v0 = *(float4*)Sr;
            float4 v1 = *(float4*)(Sr + 4);
            float vals[8] = {v0.x,v0.y,v0.z,v0.w, v1.x,v1.y,v1.z,v1.w};
            float m = vals[0];
            #pragma unroll
            for (int c = 1; c < 8; c++) m = fmaxf(m, vals[c]);
            m = fmaxf(m, __shfl_xor_sync(0xffffffffu, m, 1));
            m = fmaxf(m, __shfl_xor_sync(0xffffffffu, m, 2));
            m = fmaxf(m, __shfl_xor_sync(0xffffffffu, m, 4));
            float ssum = 0.f;
            #pragma unroll
            for (int c = 0; c < 8; c++) { vals[c] = __expf(vals[c] - m); ssum += vals[c]; }
            ssum += __shfl_xor_sync(0xffffffffu, ssum, 1);
            ssum += __shfl_xor_sync(0xffffffffu, ssum, 2);
            ssum += __shfl_xor_sync(0xffffffffu, ssum, 4);
            float inv = 1.0f / ssum;
            *(float4*)Sr = make_float4(tf32r(vals[0]*inv), tf32r(vals[1]*inv),
                                       tf32r(vals[2]*inv), tf32r(vals[3]*inv));
            *(float4*)(Sr+4) = make_float4(tf32r(vals[4]*inv), tf32r(vals[5]*inv),
                                           tf32r(vals[6]*inv), tf32r(vals[7]*inv));
        }
    }
    __syncthreads();

    // ---- Phase 5: P@V (MMA) -> ao (aliases xw) ----
    {
        float acc[3][4];
        #pragma unroll
        for (int j = 0; j < 3; j++)
            acc[j][0] = acc[j][1] = acc[j][2] = acc[j][3] = 0.f;
        #pragma unroll
        for (int j = 0; j < 3; j++) {
            int ct = ng*24 + j*8;
            int h  = ct >> 5;
            int dc = ct & 31;
            #pragma unroll
            for (int ks = 0; ks < 8; ks++) {
                const float* ap = &S3[(h*64 + 16*mt + gid)*S_LD + 8*ks];
                u32 a0 = __float_as_uint(ap[tig]);
                u32 a1 = __float_as_uint(ap[8*S_LD + tig]);
                u32 a2 = __float_as_uint(ap[tig+4]);
                u32 a3 = __float_as_uint(ap[8*S_LD + tig+4]);
                const float* bp = &qkv[(8*ks + tig)*QKV_LD + 192 + h*32 + dc + gid];
                u32 b0 = __float_as_uint(bp[0]);
                u32 b1 = __float_as_uint(bp[4*QKV_LD]);
                mma_tf32(acc[j][0], acc[j][1], acc[j][2], acc[j][3],
                         a0, a1, a2, a3, b0, b1);
            }
        }
        __syncthreads();   // xw (dead) about to be overwritten as ao
        #pragma unroll
        for (int j = 0; j < 3; j++) {
            int ct = ng*24 + j*8 + 2*tig;
            *(float2*)&ao[(16*mt + gid)*XW_LD + ct] =
                make_float2(tf32r(acc[j][0]), tf32r(acc[j][1]));
            *(float2*)&ao[(16*mt + gid + 8)*XW_LD + ct] =
                make_float2(tf32r(acc[j][2]), tf32r(acc[j][3]));
        }
    }
    __syncthreads();

    // ---- Phase 6: proj (MMA) + bias; accumulate residual in xres (smem) ----
    {
        float acc[3][4];
        #pragma unroll
        for (int j = 0; j < 3; j++)
            acc[j][0] = acc[j][1] = acc[j][2] = acc[j][3] = 0.f;
        #pragma unroll
        for (int kt = 0; kt < 12; kt++) {
            const float* ap = &ao[(16*mt + gid)*XW_LD + 8*kt];
            u32 a0 = __float_as_uint(ap[tig]);
            u32 a1 = __float_as_uint(ap[8*XW_LD + tig]);
            u32 a2 = __float_as_uint(ap[tig+4]);
            u32 a3 = __float_as_uint(ap[8*XW_LD + tig+4]);
            #pragma unroll
            for (int j = 0; j < 3; j++) {
                u64 w = Wpf[(kt*12 + ng*3 + j)*32 + lane];
                mma_tf32(acc[j][0], acc[j][1], acc[j][2], acc[j][3],
                         a0, a1, a2, a3, (u32)w, (u32)(w >> 32));
            }
        }
        // xres <- x + attn_out  (each (t,col) owned by exactly one thread)
        #pragma unroll
        for (int rr = 0; rr < 2; rr++) {
            int t = 16*mt + gid + 8*rr;
            #pragma unroll
            for (int j = 0; j < 3; j++) {
                int ct = ng*24 + j*8 + 2*tig;
                float2 bb = *(const float2*)&Bp[ct];
                float2 rv = *(float2*)&xres[t*96 + ct];
                *(float2*)&xres[t*96 + ct] = make_float2(
                    acc[j][2*rr]   + bb.x + rv.x,
                    acc[j][2*rr+1] + bb.y + rv.y);
            }
        }
    }
    __syncthreads();

    // ---- Phase 7: LN2 from xres -> y (aliases xw) ----
    for (int t = warp; t < 64; t += 16) {
        const float* src = &xres[t*96];
        float v0 = src[lane], v1 = src[lane+32], v2 = src[lane+64];
        float s  = v0 + v1 + v2;
        float sq = v0*v0 + v1*v1 + v2*v2;
        #pragma unroll
        for (int o = 16; o; o >>= 1) {
            s  += __shfl_xor_sync(0xffffffffu, s,  o);
            sq += __shfl_xor_sync(0xffffffffu, sq, o);
        }
        float mean = s * (1.0f/96.0f);
        float var  = sq * (1.0f/96.0f) - mean*mean;
        float rstd = rsqrtf(var + 1e-5f);
        y[t*XW_LD+lane]    = tf32r((v0-mean)*rstd*g2[lane]    + b2ln[lane]);
        y[t*XW_LD+lane+32] = tf32r((v1-mean)*rstd*g2[lane+32] + b2ln[lane+32]);
        y[t*XW_LD+lane+64] = tf32r((v2-mean)*rstd*g2[lane+64] + b2ln[lane+64]);
    }
    __syncthreads();

    // ---- Phase 8: MLP GEMM1 (MMA) + GELU -> hb (aliases qkv/S3, now dead) ----
    {
        float acc[12][4];
        #pragma unroll
        for (int nt = 0; nt < 12; nt++)
            acc[nt][0] = acc[nt][1] = acc[nt][2] = acc[nt][3] = 0.f;
        #pragma unroll
        for (int kt = 0; kt < 12; kt++) {
            const float* arow0 = &y[(16*mt + gid)*XW_LD + 8*kt];
            const float* arow1 = arow0 + 8*XW_LD;
            u32 a0 = __float_as_uint(arow0[tig]);
            u32 a1 = __float_as_uint(arow1[tig]);
            u32 a2 = __float_as_uint(arow0[tig+4]);
            u32 a3 = __float_as_uint(arow1[tig+4]);
            #pragma unroll
            for (int nt = 0; nt < 12; nt++) {
                u64 w = W1f[(kt*48 + ng*12 + nt)*32 + lane];
                mma_tf32(acc[nt][0], acc[nt][1], acc[nt][2], acc[nt][3],
                         a0, a1, a2, a3, (u32)w, (u32)(w >> 32));
            }
        }
        #pragma unroll
        for (int nt = 0; nt < 12; nt++) {
            int col0 = 96*ng + 8*nt + 2*tig;
            float2 bb = *(const float2*)&B1[col0];
            float u0 = acc[nt][0] + bb.x, u1 = acc[nt][1] + bb.y;
            float u2 = acc[nt][2] + bb.x, u3 = acc[nt][3] + bb.y;
            float g0 = 0.5f*u0*(1.0f + erff(u0*0.70710678118654752f));
            float g1v= 0.5f*u1*(1.0f + erff(u1*0.70710678118654752f));
            float g2v= 0.5f*u2*(1.0f + erff(u2*0.70710678118654752f));
            float g3 = 0.5f*u3*(1.0f + erff(u3*0.70710678118654752f));
            *(float2*)&hb[(16*mt + gid)*HB_LD + col0]     = make_float2(tf32r(g0), tf32r(g1v));
            *(float2*)&hb[(16*mt + gid + 8)*HB_LD + col0] = make_float2(tf32r(g2v), tf32r(g3));
        }
    }
    __syncthreads();

    // ---- Phase 9: MLP GEMM2 (MMA) + bias + residual -> out (shifted) ----
    {
        float acc[3][4];
        #pragma unroll
        for (int nt = 0; nt < 3; nt++)
            acc[nt][0] = acc[nt][1] = acc[nt][2] = acc[nt][3] = 0.f;
        #pragma unroll
        for (int kt = 0; kt < 48; kt++) {
            const float* arow0 = &hb[(16*mt + gid)*HB_LD + 8*kt];
            const float* arow1 = arow0 + 8*HB_LD;
            u32 a0 = __float_as_uint(arow0[tig]);
            u32 a1 = __float_as_uint(arow1[tig]);
            u32 a2 = __float_as_uint(arow0[tig+4]);
            u32 a3 = __float_as_uint(arow1[tig+4]);
            #pragma unroll
            for (int nt = 0; nt < 3; nt++) {
                u64 w = W2f[(kt*12 + ng*3 + nt)*32 + lane];
                mma_tf32(acc[nt][0], acc[nt][1], acc[nt][2], acc[nt][3],
                         a0, a1, a2, a3, (u32)w, (u32)(w >> 32));
            }
        }
        #pragma unroll
        for (int rr = 0; rr < 2; rr++) {
            int t = 16*mt + gid + 8*rr;
            int td = t >> 4, th = (t >> 2) & 3, tw = t & 3;
            int gd = (wd*4 + td + shift) & 63;
            int gh = (wh*4 + th + shift) & 63;
            int gw = (ww*4 + tw + shift) & 63;
            size_t idx = (size_t)((((b*64 + gd)*64 + gh)*64 + gw)) * 96;
            float* dst = out + idx;
            #pragma unroll
            for (int nt = 0; nt < 3; nt++) {
                int ct = 24*ng + 8*nt + 2*tig;
                float2 bb = *(const float2*)&B2[ct];
                float2 rv = *(float2*)&xres[t*96 + ct];
                *(float2*)&dst[ct] = make_float2(
                    acc[nt][2*rr]   + bb.x + rv.x,
                    acc[nt][2*rr+1] + bb.y + rv.y);
            }
        }
    }
}

// ---------------------------------------------------------------------------
extern "C" void kernel_launch(void* const* d_in, const int* in_sizes, int n_in,
                              void* d_out, int out_size)
{
    const float* x      = (const float*)d_in[0];
    const float* qkv_w  = (const float*)d_in[1];
    const float* qkv_b  = (const float*)d_in[2];
    const float* proj_w = (const float*)d_in[3];
    const float* proj_b = (const float*)d_in[4];
    const float* btab   = (const float*)d_in[5];
    const float* ln1g   = (const float*)d_in[6];
    const float* ln1b   = (const float*)d_in[7];
    const float* ln2g   = (const float*)d_in[8];
    const float* ln2b   = (const float*)d_in[9];
    const float* w1     = (const float*)d_in[10];
    const float* b1     = (const float*)d_in[11];
    const float* w2     = (const float*)d_in[12];
    const float* b2     = (const float*)d_in[13];
    float* out = (float*)d_out;

    float* scratch = nullptr;
    u64 *wqkvf = nullptr, *w1f = nullptr, *w2f = nullptr, *wpf = nullptr;
    float* biasm = nullptr;
    cudaGetSymbolAddress((void**)&scratch, g_scratch);
    cudaGetSymbolAddress((void**)&wqkvf,   g_wqkvf);
    cudaGetSymbolAddress((void**)&w1f,     g_w1f);
    cudaGetSymbolAddress((void**)&w2f,     g_w2f);
    cudaGetSymbolAddress((void**)&wpf,     g_wpf);
    cudaGetSymbolAddress((void**)&biasm,   g_bias);

    cudaFuncSetAttribute(block_kernel, cudaFuncAttributeMaxDynamicSharedMemorySize, FSMEM);

    // Prep: fragment-pack weights + dense bias matrices
    {
        int tq = 2*12*36*32, t1 = 2*12*48*32, t2 = 2*48*12*32, tp = 2*12*12*32;
        pack_kernel<<<(tq+255)/256, 256>>>(qkv_w, wqkvf, 12, 36, 288, tq);
        pack_kernel<<<(t1+255)/256, 256>>>(w1,    w1f,   12, 48, 384, t1);
        pack_kernel<<<(t2+255)/256, 256>>>(w2,    w2f,   48, 12,  96, t2);
        pack_kernel<<<(tp+255)/256, 256>>>(proj_w, wpf,  12, 12,  96, tp);
        bias_kernel<<<(2*3*64*64+255)/256, 256>>>(btab);
    }

    // ---- block 0 (shift 0): x -> scratch ----
    block_kernel<<<NWIN, 512, FSMEM>>>(x, scratch,
        wqkvf, qkv_b, wpf, proj_b, biasm, ln1g, ln1b,
        ln2g, ln2b, w1f, b1, w2f, b2, 0);

    // ---- block 1 (shift 2): scratch -> out ----
    block_kernel<<<NWIN, 512, FSMEM>>>(scratch, out,
        wqkvf + 12*36*32, qkv_b + 288, wpf + 12*12*32, proj_b + 96,
        biasm + 3*64*64, ln1g + 96, ln1b + 96,
        ln2g + 96, ln2b + 96, w1f + 12*48*32, b1 + 384, w2f + 48*12*32, b2 + 96, 2);
}

// round 15
// speedup vs baseline: 1.0590x; 1.0005x over previous
#include <cuda_runtime.h>
#include <math.h>

typedef unsigned long long u64;
typedef unsigned int u32;

#define CDIM   96
#define NWIN   8192
#define TOKENS (2*64*64*64)
#define QKV_LD 292          // %32==4, 16B-aligned rows
#define S_LD   68
#define XW_LD  100          // %32==4 -> conflict-free mma A-fragment LDS
#define HB_LD  388          // %32==4

// Static device scratch (no allocs allowed)
__device__ float g_scratch[(size_t)TOKENS * CDIM];
// Fragment-packed tf32 weights (u64 = {b0 lo, b1 hi})
__device__ u64 g_wqkvf[2 * 12 * 36 * 32];   // K=96 (KT12), N=288 (NT36)
__device__ u64 g_w1f  [2 * 12 * 48 * 32];   // K=96,  N=384
__device__ u64 g_w2f  [2 * 48 * 12 * 32];   // K=384, N=96
__device__ u64 g_wpf  [2 * 12 * 12 * 32];   // K=96,  N=96 (proj)
// Dense rel-pos bias: [layer][head][q=64][k=64]
__device__ float g_bias[2 * 3 * 64 * 64];

// Fused-kernel smem: xres(6144) + xw(6400) + qkv(18688) + S3(13056)
#define FSMEM ((64*96 + 64*XW_LD + 64*QKV_LD + 3*64*S_LD) * 4)

// ---- tf32 helpers ----
__device__ __forceinline__ u32 tf32bits(float x) {
    u32 r; asm("cvt.rna.tf32.f32 %0,%1;" : "=r"(r) : "f"(x)); return r;
}
__device__ __forceinline__ float tf32r(float x) {
    return __uint_as_float(tf32bits(x));
}
__device__ __forceinline__ void mma_tf32(
    float& c0, float& c1, float& c2, float& c3,
    u32 a0, u32 a1, u32 a2, u32 a3, u32 b0, u32 b1)
{
    asm("mma.sync.aligned.m16n8k8.row.col.f32.tf32.tf32.f32 "
        "{%0,%1,%2,%3},{%4,%5,%6,%7},{%8,%9},{%0,%1,%2,%3};"
        : "+f"(c0), "+f"(c1), "+f"(c2), "+f"(c3)
        : "r"(a0), "r"(a1), "r"(a2), "r"(a3), "r"(b0), "r"(b1));
}

// ---------------------------------------------------------------------------
// Pack row-major W[K][N] (per layer) into mma B-fragment order.
// ---------------------------------------------------------------------------
__global__ void pack_kernel(const float* __restrict__ W, u64* __restrict__ dst,
                            int KT, int NT, int N, int total)
{
    int i = blockIdx.x * blockDim.x + threadIdx.x;
    if (i >= total) return;
    int per_layer = KT * NT * 32;
    int layer = i / per_layer;
    int r = i - layer * per_layer;
    int t = r >> 5, lane = r & 31;
    int kt = t / NT, nt = t - kt * NT;
    int k = kt * 8 + (lane & 3);
    int n = nt * 8 + (lane >> 2);
    const float* Wl = W + (size_t)layer * (KT * 8) * N;
    u32 lo = tf32bits(Wl[(size_t)k * N + n]);
    u32 hi = tf32bits(Wl[(size_t)(k + 4) * N + n]);
    dst[i] = ((u64)hi << 32) | lo;
}

// ---------------------------------------------------------------------------
// Precompute dense rel-pos bias matrices (window-invariant).
// ---------------------------------------------------------------------------
__global__ void bias_kernel(const float* __restrict__ tb) {
    int i = blockIdx.x * blockDim.x + threadIdx.x;
    if (i >= 2*3*64*64) return;
    int layer = i / (3*4096);
    int r = i % (3*4096);
    int h = r / 4096;
    int qk = r & 4095;
    int q = qk >> 6, k = qk & 63;
    int qd = q >> 4, qh = (q >> 2) & 3, qw = q & 3;
    int kd = k >> 4, kh = (k >> 2) & 3, kw = k & 3;
    int ridx = (qd-kd+3)*49 + (qh-kh+3)*7 + (qw-kw+3);
    g_bias[i] = tb[layer*1029 + ridx*3 + h];
}

// ---------------------------------------------------------------------------
// Fully fused Swin block: LN1 -> QKV -> S(+bias) -> softmax -> P@V -> proj
// -> +residual (smem) -> LN2 -> MLP(GEMM1+GELU+GEMM2) -> +residual -> out.
// One CTA per 4x4x4 window, 512 threads (16 warps: mt=warp&3, ng=warp>>2).
// Reads x once, writes out once.
// ---------------------------------------------------------------------------
__global__ __launch_bounds__(512, 1) void block_kernel(
    const float* __restrict__ x, float* __restrict__ out,
    const u64*  __restrict__ Wqkvf, const float* __restrict__ Bqkv,
    const u64*  __restrict__ Wpf,   const float* __restrict__ Bp,
    const float* __restrict__ biasM,
    const float* __restrict__ g1,   const float* __restrict__ b1,
    const float* __restrict__ g2,   const float* __restrict__ b2ln,
    const u64*  __restrict__ W1f,   const float* __restrict__ B1,
    const u64*  __restrict__ W2f,   const float* __restrict__ B2,
    int shift)
{
    extern __shared__ float sm[];
    float* xres = sm;                    // 64 x 96: raw x, later x+attn (residual)
    float* xw   = xres + 64*96;          // 64 x XW_LD: LN1 out; aliased ao, then y
    float* qkv  = xw + 64*XW_LD;         // 64 x 292 (tf32-rounded)
    float* S3   = qkv + 64*QKV_LD;       // 3 x 64 x 68
    float* ao   = xw;
    float* y    = xw;
    float* hb   = qkv;                   // 64 x HB_LD aliases qkv+S3 (dead by then)

    const int tid  = threadIdx.x;
    const int lane = tid & 31;
    const int warp = tid >> 5;
    const int mt   = warp & 3;
    const int ng   = warp >> 2;
    const int gid  = lane >> 2;
    const int tig  = lane & 3;

    const int bw   = blockIdx.x;
    const int b    = bw >> 12;
    const int widx = bw & 4095;
    const int wd   = widx >> 8;
    const int wh   = (widx >> 4) & 15;
    const int ww   = widx & 15;

    // ---- Phase 1: load x (shifted) + LN1; keep raw x in xres ----
    for (int t = warp; t < 64; t += 16) {
        int td = t >> 4, th = (t >> 2) & 3, tw = t & 3;
        int gd = (wd*4 + td + shift) & 63;
        int gh = (wh*4 + th + shift) & 63;
        int gw = (ww*4 + tw + shift) & 63;
        const float* src = x + (size_t)((((b*64 + gd)*64 + gh)*64 + gw)) * 96;
        float v0 = src[lane], v1 = src[lane+32], v2 = src[lane+64];
        float s  = v0 + v1 + v2;
        float sq = v0*v0 + v1*v1 + v2*v2;
        #pragma unroll
        for (int o = 16; o; o >>= 1) {
            s  += __shfl_xor_sync(0xffffffffu, s,  o);
            sq += __shfl_xor_sync(0xffffffffu, sq, o);
        }
        float mean = s * (1.0f/96.0f);
        float var  = sq * (1.0f/96.0f) - mean*mean;
        float rstd = rsqrtf(var + 1e-5f);
        xres[t*96+lane]    = v0;
        xres[t*96+lane+32] = v1;
        xres[t*96+lane+64] = v2;
        xw[t*XW_LD+lane]    = tf32r((v0-mean)*rstd*g1[lane]    + b1[lane]);
        xw[t*XW_LD+lane+32] = tf32r((v1-mean)*rstd*g1[lane+32] + b1[lane+32]);
        xw[t*XW_LD+lane+64] = tf32r((v2-mean)*rstd*g1[lane+64] + b1[lane+64]);
    }
    __syncthreads();

    // ---- Phase 2: QKV GEMM (MMA), 9 n-tiles/warp; q pre-scaled, tf32-rounded ----
    {
        float acc[9][4];
        #pragma unroll
        for (int nt = 0; nt < 9; nt++) {
            int col0 = 72*ng + 8*nt + 2*tig;
            float2 bb = *(const float2*)&Bqkv[col0];
            acc[nt][0] = bb.x; acc[nt][1] = bb.y;
            acc[nt][2] = bb.x; acc[nt][3] = bb.y;
        }
        #pragma unroll
        for (int kt = 0; kt < 12; kt++) {
            const float* arow0 = &xw[(16*mt + gid)*XW_LD + 8*kt];
            const float* arow1 = arow0 + 8*XW_LD;
            u32 a0 = __float_as_uint(arow0[tig]);
            u32 a1 = __float_as_uint(arow1[tig]);
            u32 a2 = __float_as_uint(arow0[tig+4]);
            u32 a3 = __float_as_uint(arow1[tig+4]);
            #pragma unroll
            for (int nt = 0; nt < 9; nt++) {
                u64 w = Wqkvf[(kt*36 + ng*9 + nt)*32 + lane];
                mma_tf32(acc[nt][0], acc[nt][1], acc[nt][2], acc[nt][3],
                         a0, a1, a2, a3, (u32)w, (u32)(w >> 32));
            }
        }
        const float qs = 0.17677669529663687f;  // 32^-0.5
        #pragma unroll
        for (int nt = 0; nt < 9; nt++) {
            int col0 = 72*ng + 8*nt + 2*tig;
            float sc = (72*ng + 8*nt < 96) ? qs : 1.0f;
            *(float2*)&qkv[(16*mt + gid)*QKV_LD + col0] =
                make_float2(tf32r(acc[nt][0]*sc), tf32r(acc[nt][1]*sc));
            *(float2*)&qkv[(16*mt + gid + 8)*QKV_LD + col0] =
                make_float2(tf32r(acc[nt][2]*sc), tf32r(acc[nt][3]*sc));
        }
    }
    __syncthreads();

    // ---- Phase 3: S = qK^T + bias (MMA), per head ng covers 16 cols ----
    #pragma unroll
    for (int h = 0; h < 3; h++) {
        float acc[2][4];
        #pragma unroll
        for (int j = 0; j < 2; j++)
            acc[j][0] = acc[j][1] = acc[j][2] = acc[j][3] = 0.f;
        #pragma unroll
        for (int ks = 0; ks < 4; ks++) {
            const float* ap = &qkv[(16*mt + gid)*QKV_LD + h*32 + 8*ks];
            u32 a0 = __float_as_uint(ap[tig]);
            u32 a1 = __float_as_uint(ap[8*QKV_LD + tig]);
            u32 a2 = __float_as_uint(ap[tig+4]);
            u32 a3 = __float_as_uint(ap[8*QKV_LD + tig+4]);
            #pragma unroll
            for (int j = 0; j < 2; j++) {
                const float* bp = &qkv[(ng*16 + j*8 + gid)*QKV_LD + 96 + h*32 + 8*ks];
                u32 b0 = __float_as_uint(bp[tig]);
                u32 b1 = __float_as_uint(bp[tig+4]);
                mma_tf32(acc[j][0], acc[j][1], acc[j][2], acc[j][3],
                         a0, a1, a2, a3, b0, b1);
            }
        }
        const float* bh = biasM + h*4096;
        #pragma unroll
        for (int j = 0; j < 2; j++) {
            int col = ng*16 + j*8 + 2*tig;
            int q0  = 16*mt + gid;
            float2 bb0 = *(const float2*)&bh[q0*64 + col];
            float2 bb1 = *(const float2*)&bh[(q0+8)*64 + col];
            *(float2*)&S3[(h*64 + q0)*S_LD + col] =
                make_float2(acc[j][0] + bb0.x, acc[j][1] + bb0.y);
            *(float2*)&S3[(h*64 + q0 + 8)*S_LD + col] =
                make_float2(acc[j][2] + bb1.x, acc[j][3] + bb1.y);
        }
    }
    __syncthreads();

    // ---- Phase 4: softmax (8 lanes/row), probs tf32-rounded ----
    {
        int row = tid >> 3, sub = tid & 7;
        #pragma unroll
        for (int h = 0; h < 3; h++) {
            float* Sr = &S3[(h*64 + row)*S_LD + sub*8];
            float4 v0 = *(float4*)Sr;
            float4 v1 = *(float4*)(Sr + 4);
            float vals[8] = {v0.x,v0.y,v0.z,v0.w, v1.x,v1.y,v1.z,v1.w};
            float m = vals[0];
            #pragma unroll
            for (int c = 1; c < 8; c++) m = fmaxf(m, vals[c]);
            m = fmaxf(m, __shfl_xor_sync(0xffffffffu, m, 1));
            m = fmaxf(m, __shfl_xor_sync(0xffffffffu, m, 2));
            m = fmaxf(m, __shfl_xor_sync(0xffffffffu, m, 4));
            float ssum = 0.f;
            #pragma unroll
            for (int c = 0; c < 8; c++) { vals[c] = __expf(vals[c] - m); ssum += vals[c]; }
            ssum += __shfl_xor_sync(0xffffffffu, ssum, 1);
            ssum += __shfl_xor_sync(0xffffffffu, ssum, 2);
            ssum += __shfl_xor_sync(0xffffffffu, ssum, 4);
            float inv = 1.0f / ssum;
            *(float4*)Sr = make_float4(tf32r(vals[0]*inv), tf32r(vals[1]*inv),
                                       tf32r(vals[2]*inv), tf32r(vals[3]*inv));
            *(float4*)(Sr+4) = make_float4(tf32r(vals[4]*inv), tf32r(vals[5]*inv),
                                           tf32r(vals[6]*inv), tf32r(vals[7]*inv));
        }
    }
    __syncthreads();

    // ---- Phase 5: P@V (MMA) -> ao (aliases xw) ----
    {
        float acc[3][4];
        #pragma unroll
        for (int j = 0; j < 3; j++)
            acc[j][0] = acc[j][1] = acc[j][2] = acc[j][3] = 0.f;
        #pragma unroll
        for (int j = 0; j < 3; j++) {
            int ct = ng*24 + j*8;
            int h  = ct >> 5;
            int dc = ct & 31;
            #pragma unroll
            for (int ks = 0; ks < 8; ks++) {
                const float* ap = &S3[(h*64 + 16*mt + gid)*S_LD + 8*ks];
                u32 a0 = __float_as_uint(ap[tig]);
                u32 a1 = __float_as_uint(ap[8*S_LD + tig]);
                u32 a2 = __float_as_uint(ap[tig+4]);
                u32 a3 = __float_as_uint(ap[8*S_LD + tig+4]);
                const float* bp = &qkv[(8*ks + tig)*QKV_LD + 192 + h*32 + dc + gid];
                u32 b0 = __float_as_uint(bp[0]);
                u32 b1 = __float_as_uint(bp[4*QKV_LD]);
                mma_tf32(acc[j][0], acc[j][1], acc[j][2], acc[j][3],
                         a0, a1, a2, a3, b0, b1);
            }
        }
        __syncthreads();   // xw (dead) about to be overwritten as ao
        #pragma unroll
        for (int j = 0; j < 3; j++) {
            int ct = ng*24 + j*8 + 2*tig;
            *(float2*)&ao[(16*mt + gid)*XW_LD + ct] =
                make_float2(tf32r(acc[j][0]), tf32r(acc[j][1]));
            *(float2*)&ao[(16*mt + gid + 8)*XW_LD + ct] =
                make_float2(tf32r(acc[j][2]), tf32r(acc[j][3]));
        }
    }
    __syncthreads();

    // ---- Phase 6: proj (MMA) + bias; accumulate residual in xres (smem) ----
    {
        float acc[3][4];
        #pragma unroll
        for (int j = 0; j < 3; j++)
            acc[j][0] = acc[j][1] = acc[j][2] = acc[j][3] = 0.f;
        #pragma unroll
        for (int kt = 0; kt < 12; kt++) {
            const float* ap = &ao[(16*mt + gid)*XW_LD + 8*kt];
            u32 a0 = __float_as_uint(ap[tig]);
            u32 a1 = __float_as_uint(ap[8*XW_LD + tig]);
            u32 a2 = __float_as_uint(ap[tig+4]);
            u32 a3 = __float_as_uint(ap[8*XW_LD + tig+4]);
            #pragma unroll
            for (int j = 0; j < 3; j++) {
                u64 w = Wpf[(kt*12 + ng*3 + j)*32 + lane];
                mma_tf32(acc[j][0], acc[j][1], acc[j][2], acc[j][3],
                         a0, a1, a2, a3, (u32)w, (u32)(w >> 32));
            }
        }
        // xres <- x + attn_out  (each (t,col) owned by exactly one thread)
        #pragma unroll
        for (int rr = 0; rr < 2; rr++) {
            int t = 16*mt + gid + 8*rr;
            #pragma unroll
            for (int j = 0; j < 3; j++) {
                int ct = ng*24 + j*8 + 2*tig;
                float2 bb = *(const float2*)&Bp[ct];
                float2 rv = *(float2*)&xres[t*96 + ct];
                *(float2*)&xres[t*96 + ct] = make_float2(
                    acc[j][2*rr]   + bb.x + rv.x,
                    acc[j][2*rr+1] + bb.y + rv.y);
            }
        }
    }
    __syncthreads();

    // ---- Phase 7: LN2 from xres -> y (aliases xw) ----
    for (int t = warp; t < 64; t += 16) {
        const float* src = &xres[t*96];
        float v0 = src[lane], v1 = src[lane+32], v2 = src[lane+64];
        float s  = v0 + v1 + v2;
        float sq = v0*v0 + v1*v1 + v2*v2;
        #pragma unroll
        for (int o = 16; o; o >>= 1) {
            s  += __shfl_xor_sync(0xffffffffu, s,  o);
            sq += __shfl_xor_sync(0xffffffffu, sq, o);
        }
        float mean = s * (1.0f/96.0f);
        float var  = sq * (1.0f/96.0f) - mean*mean;
        float rstd = rsqrtf(var + 1e-5f);
        y[t*XW_LD+lane]    = tf32r((v0-mean)*rstd*g2[lane]    + b2ln[lane]);
        y[t*XW_LD+lane+32] = tf32r((v1-mean)*rstd*g2[lane+32] + b2ln[lane+32]);
        y[t*XW_LD+lane+64] = tf32r((v2-mean)*rstd*g2[lane+64] + b2ln[lane+64]);
    }
    __syncthreads();

    // ---- Phase 8: MLP GEMM1 (MMA) + GELU -> hb (aliases qkv/S3, now dead) ----
    {
        float acc[12][4];
        #pragma unroll
        for (int nt = 0; nt < 12; nt++)
            acc[nt][0] = acc[nt][1] = acc[nt][2] = acc[nt][3] = 0.f;
        #pragma unroll
        for (int kt = 0; kt < 12; kt++) {
            const float* arow0 = &y[(16*mt + gid)*XW_LD + 8*kt];
            const float* arow1 = arow0 + 8*XW_LD;
            u32 a0 = __float_as_uint(arow0[tig]);
            u32 a1 = __float_as_uint(arow1[tig]);
            u32 a2 = __float_as_uint(arow0[tig+4]);
            u32 a3 = __float_as_uint(arow1[tig+4]);
            #pragma unroll
            for (int nt = 0; nt < 12; nt++) {
                u64 w = W1f[(kt*48 + ng*12 + nt)*32 + lane];
                mma_tf32(acc[nt][0], acc[nt][1], acc[nt][2], acc[nt][3],
                         a0, a1, a2, a3, (u32)w, (u32)(w >> 32));
            }
        }
        #pragma unroll
        for (int nt = 0; nt < 12; nt++) {
            int col0 = 96*ng + 8*nt + 2*tig;
            float2 bb = *(const float2*)&B1[col0];
            float u0 = acc[nt][0] + bb.x, u1 = acc[nt][1] + bb.y;
            float u2 = acc[nt][2] + bb.x, u3 = acc[nt][3] + bb.y;
            float g0 = 0.5f*u0*(1.0f + erff(u0*0.70710678118654752f));
            float g1v= 0.5f*u1*(1.0f + erff(u1*0.70710678118654752f));
            float g2v= 0.5f*u2*(1.0f + erff(u2*0.70710678118654752f));
            float g3 = 0.5f*u3*(1.0f + erff(u3*0.70710678118654752f));
            *(float2*)&hb[(16*mt + gid)*HB_LD + col0]     = make_float2(tf32r(g0), tf32r(g1v));
            *(float2*)&hb[(16*mt + gid + 8)*HB_LD + col0] = make_float2(tf32r(g2v), tf32r(g3));
        }
    }
    __syncthreads();

    // ---- Phase 9: MLP GEMM2 (MMA) + bias + residual -> out (shifted) ----
    {
        float acc[3][4];
        #pragma unroll
        for (int nt = 0; nt < 3; nt++)
            acc[nt][0] = acc[nt][1] = acc[nt][2] = acc[nt][3] = 0.f;
        #pragma unroll
        for (int kt = 0; kt < 48; kt++) {
            const float* arow0 = &hb[(16*mt + gid)*HB_LD + 8*kt];
            const float* arow1 = arow0 + 8*HB_LD;
            u32 a0 = __float_as_uint(arow0[tig]);
            u32 a1 = __float_as_uint(arow1[tig]);
            u32 a2 = __float_as_uint(arow0[tig+4]);
            u32 a3 = __float_as_uint(arow1[tig+4]);
            #pragma unroll
            for (int nt = 0; nt < 3; nt++) {
                u64 w = W2f[(kt*12 + ng*3 + nt)*32 + lane];
                mma_tf32(acc[nt][0], acc[nt][1], acc[nt][2], acc[nt][3],
                         a0, a1, a2, a3, (u32)w, (u32)(w >> 32));
            }
        }
        #pragma unroll
        for (int rr = 0; rr < 2; rr++) {
            int t = 16*mt + gid + 8*rr;
            int td = t >> 4, th = (t >> 2) & 3, tw = t & 3;
            int gd = (wd*4 + td + shift) & 63;
            int gh = (wh*4 + th + shift) & 63;
            int gw = (ww*4 + tw + shift) & 63;
            size_t idx = (size_t)((((b*64 + gd)*64 + gh)*64 + gw)) * 96;
            float* dst = out + idx;
            #pragma unroll
            for (int nt = 0; nt < 3; nt++) {
                int ct = 24*ng + 8*nt + 2*tig;
                float2 bb = *(const float2*)&B2[ct];
                float2 rv = *(float2*)&xres[t*96 + ct];
                *(float2*)&dst[ct] = make_float2(
                    acc[nt][2*rr]   + bb.x + rv.x,
                    acc[nt][2*rr+1] + bb.y + rv.y);
            }
        }
    }
}

// ---------------------------------------------------------------------------
extern "C" void kernel_launch(void* const* d_in, const int* in_sizes, int n_in,
                              void* d_out, int out_size)
{
    const float* x      = (const float*)d_in[0];
    const float* qkv_w  = (const float*)d_in[1];
    const float* qkv_b  = (const float*)d_in[2];
    const float* proj_w = (const float*)d_in[3];
    const float* proj_b = (const float*)d_in[4];
    const float* btab   = (const float*)d_in[5];
    const float* ln1g   = (const float*)d_in[6];
    const float* ln1b   = (const float*)d_in[7];
    const float* ln2g   = (const float*)d_in[8];
    const float* ln2b   = (const float*)d_in[9];
    const float* w1     = (const float*)d_in[10];
    const float* b1     = (const float*)d_in[11];
    const float* w2     = (const float*)d_in[12];
    const float* b2     = (const float*)d_in[13];
    float* out = (float*)d_out;

    float* scratch = nullptr;
    u64 *wqkvf = nullptr, *w1f = nullptr, *w2f = nullptr, *wpf = nullptr;
    float* biasm = nullptr;
    cudaGetSymbolAddress((void**)&scratch, g_scratch);
    cudaGetSymbolAddress((void**)&wqkvf,   g_wqkvf);
    cudaGetSymbolAddress((void**)&w1f,     g_w1f);
    cudaGetSymbolAddress((void**)&w2f,     g_w2f);
    cudaGetSymbolAddress((void**)&wpf,     g_wpf);
    cudaGetSymbolAddress((void**)&biasm,   g_bias);

    cudaFuncSetAttribute(block_kernel, cudaFuncAttributeMaxDynamicSharedMemorySize, FSMEM);

    // Prep: fragment-pack weights + dense bias matrices
    {
        int tq = 2*12*36*32, t1 = 2*12*48*32, t2 = 2*48*12*32, tp = 2*12*12*32;
        pack_kernel<<<(tq+255)/256, 256>>>(qkv_w, wqkvf, 12, 36, 288, tq);
        pack_kernel<<<(t1+255)/256, 256>>>(w1,    w1f,   12, 48, 384, t1);
        pack_kernel<<<(t2+255)/256, 256>>>(w2,    w2f,   48, 12,  96, t2);
        pack_kernel<<<(tp+255)/256, 256>>>(proj_w, wpf,  12, 12,  96, tp);
        bias_kernel<<<(2*3*64*64+255)/256, 256>>>(btab);
    }

    // ---- block 0 (shift 0): x -> scratch ----
    block_kernel<<<NWIN, 512, FSMEM>>>(x, scratch,
        wqkvf, qkv_b, wpf, proj_b, biasm, ln1g, ln1b,
        ln2g, ln2b, w1f, b1, w2f, b2, 0);

    // ---- block 1 (shift 2): scratch -> out ----
    block_kernel<<<NWIN, 512, FSMEM>>>(scratch, out,
        wqkvf + 12*36*32, qkv_b + 288, wpf + 12*12*32, proj_b + 96,
        biasm + 3*64*64, ln1g + 96, ln1b + 96,
        ln2g + 96, ln2b + 96, w1f + 12*48*32, b1 + 384, w2f + 48*12*32, b2 + 96, 2);
}

// round 17
// speedup vs baseline: 1.8557x; 1.7523x over previous
#include <cuda_runtime.h>
#include <cuda_bf16.h>
#include <math.h>

typedef unsigned long long u64;
typedef unsigned int u32;

#define NWIN   8192
#define TOKENS (2*64*64*64)

// bf16 element strides (rows bytes: *2)
#define XW_LD 104   // 208 B/row
#define QK_LD 200   // 400 B/row
#define VT_LD 72    // 144 B/row
#define P_LD  72    // 144 B/row
#define HB_LD 392   // 784 B/row

// Static device scratch
__device__ float g_scratch[(size_t)TOKENS * 96];
// bf16 fragment-packed weights: u64 = {b0(lo pair), b1(hi pair)} per (k16-tile, n8-tile, lane)
__device__ u64 g_wqkvf[2 * 6 * 36 * 32];
__device__ u64 g_w1f  [2 * 6 * 48 * 32];
__device__ u64 g_w2f  [2 * 24 * 12 * 32];
__device__ u64 g_wpf  [2 * 6 * 12 * 32];
__device__ float g_bias[2 * 3 * 64 * 64];

// smem byte offsets
#define OFF_XRES 0                    // fp32 64x96          = 24576
#define OFF_XW   24576                // bf16 64x104         = 13312 (xw/ao/y)
#define OFF_QK   37888                // bf16 64x200 (Q|K)   = 25600
#define OFF_VT   63488                // bf16 96x72 (V^T)    = 13824
#define OFF_P    77312                // bf16 3x64x72 probs  = 27648
#define OFF_RMAX 104960               // fp32 192x2          = 1536
#define OFF_RSUM 106496               // fp32 192x2          = 1536
#define FSMEM    108032
#define OFF_HB   OFF_QK               // bf16 64x392 = 50176 aliases QK+VT+P

#define LD32(off) (*(const u32*)(smc + (off)))

__device__ __forceinline__ u32 bf2(float lo, float hi) {
    u32 r; asm("cvt.rn.bf16x2.f32 %0,%1,%2;" : "=r"(r) : "f"(hi), "f"(lo)); return r;
}
__device__ __forceinline__ void mma_bf16(float* c,
    u32 a0, u32 a1, u32 a2, u32 a3, u32 b0, u32 b1)
{
    asm("mma.sync.aligned.m16n8k16.row.col.f32.bf16.bf16.f32 "
        "{%0,%1,%2,%3},{%4,%5,%6,%7},{%8,%9},{%0,%1,%2,%3};"
        : "+f"(c[0]), "+f"(c[1]), "+f"(c[2]), "+f"(c[3])
        : "r"(a0), "r"(a1), "r"(a2), "r"(a3), "r"(b0), "r"(b1));
}

// ---------------------------------------------------------------------------
// Pack row-major W[K][N] (per layer) into m16n8k16 bf16 B-fragment order.
// ---------------------------------------------------------------------------
__global__ void pack_kernel(const float* __restrict__ W, u64* __restrict__ dst,
                            int KT, int NT, int N, int total)
{
    int i = blockIdx.x * blockDim.x + threadIdx.x;
    if (i >= total) return;
    int per_layer = KT * NT * 32;
    int layer = i / per_layer;
    int r = i - layer * per_layer;
    int t = r >> 5, lane = r & 31;
    int kt = t / NT, nt = t - kt * NT;
    int k0 = kt * 16 + 2 * (lane & 3);
    int n  = nt * 8 + (lane >> 2);
    const float* Wl = W + (size_t)layer * (KT * 16) * N;
    u32 lo = bf2(Wl[(size_t)k0 * N + n],     Wl[(size_t)(k0+1) * N + n]);
    u32 hi = bf2(Wl[(size_t)(k0+8) * N + n], Wl[(size_t)(k0+9) * N + n]);
    dst[i] = ((u64)hi << 32) | lo;
}

// ---------------------------------------------------------------------------
// Dense rel-pos bias (window-invariant).
// ---------------------------------------------------------------------------
__global__ void bias_kernel(const float* __restrict__ tb) {
    int i = blockIdx.x * blockDim.x + threadIdx.x;
    if (i >= 2*3*64*64) return;
    int layer = i / (3*4096);
    int r = i % (3*4096);
    int h = r / 4096;
    int qk = r & 4095;
    int q = qk >> 6, k = qk & 63;
    int qd = q >> 4, qh = (q >> 2) & 3, qw = q & 3;
    int kd = k >> 4, kh = (k >> 2) & 3, kw = k & 3;
    int ridx = (qd-kd+3)*49 + (qh-kh+3)*7 + (qw-kw+3);
    g_bias[i] = tb[layer*1029 + ridx*3 + h];
}

// ---------------------------------------------------------------------------
// Fully fused Swin block, bf16 tensor-core path, 2 CTAs/SM.
// One CTA per 4x4x4 window, 256 threads (8 warps: mt=warp&3, ng2=warp>>2).
// ---------------------------------------------------------------------------
__global__ __launch_bounds__(256, 2) void block_kernel(
    const float* __restrict__ x, float* __restrict__ out,
    const u64*  __restrict__ Wqkvf, const float* __restrict__ Bqkv,
    const u64*  __restrict__ Wpf,   const float* __restrict__ Bp,
    const float* __restrict__ biasM,
    const float* __restrict__ g1,   const float* __restrict__ b1,
    const float* __restrict__ g2,   const float* __restrict__ b2ln,
    const u64*  __restrict__ W1f,   const float* __restrict__ B1,
    const u64*  __restrict__ W2f,   const float* __restrict__ B2,
    int shift)
{
    extern __shared__ char smc[];
    float* xres = (float*)(smc + OFF_XRES);
    float* rmax = (float*)(smc + OFF_RMAX);
    float* rsum = (float*)(smc + OFF_RSUM);
    __nv_bfloat16* xw = (__nv_bfloat16*)(smc + OFF_XW);
    __nv_bfloat16* vt = (__nv_bfloat16*)(smc + OFF_VT);

    const int tid  = threadIdx.x;
    const int lane = tid & 31;
    const int warp = tid >> 5;
    const int mt   = warp & 3;
    const int ng2  = warp >> 2;     // 0..1
    const int gid  = lane >> 2;
    const int tig  = lane & 3;
    const int r0   = 16*mt + gid;
    const int r1   = r0 + 8;

    const int bw   = blockIdx.x;
    const int b    = bw >> 12;
    const int widx = bw & 4095;
    const int wd   = widx >> 8;
    const int wh   = (widx >> 4) & 15;
    const int ww   = widx & 15;

    // ---- Phase 1: load x (shifted) + LN1 -> xw (bf16), raw x -> xres ----
    for (int t = warp; t < 64; t += 8) {
        int td = t >> 4, th = (t >> 2) & 3, tw = t & 3;
        int gd = (wd*4 + td + shift) & 63;
        int gh = (wh*4 + th + shift) & 63;
        int gw = (ww*4 + tw + shift) & 63;
        const float* src = x + (size_t)((((b*64 + gd)*64 + gh)*64 + gw)) * 96;
        float v0 = src[lane], v1 = src[lane+32], v2 = src[lane+64];
        float s  = v0 + v1 + v2;
        float sq = v0*v0 + v1*v1 + v2*v2;
        #pragma unroll
        for (int o = 16; o; o >>= 1) {
            s  += __shfl_xor_sync(0xffffffffu, s,  o);
            sq += __shfl_xor_sync(0xffffffffu, sq, o);
        }
        float mean = s * (1.0f/96.0f);
        float var  = sq * (1.0f/96.0f) - mean*mean;
        float rstd = rsqrtf(var + 1e-5f);
        xres[t*96+lane]    = v0;
        xres[t*96+lane+32] = v1;
        xres[t*96+lane+64] = v2;
        xw[t*XW_LD+lane]    = __float2bfloat16((v0-mean)*rstd*g1[lane]    + b1[lane]);
        xw[t*XW_LD+lane+32] = __float2bfloat16((v1-mean)*rstd*g1[lane+32] + b1[lane+32]);
        xw[t*XW_LD+lane+64] = __float2bfloat16((v2-mean)*rstd*g1[lane+64] + b1[lane+64]);
    }
    __syncthreads();

    // ---- Phase 2: QKV GEMM (bf16 MMA, 2 passes x 9 n-tiles) ----
    {
        const float qs = 0.17677669529663687f;  // 32^-0.5
        for (int pass = 0; pass < 2; pass++) {
            float acc[9][4];
            #pragma unroll
            for (int n = 0; n < 9; n++)
                acc[n][0]=acc[n][1]=acc[n][2]=acc[n][3]=0.f;
            #pragma unroll
            for (int kt = 0; kt < 6; kt++) {
                int ab = OFF_XW + r0*208 + kt*32 + tig*4;
                u32 a0 = LD32(ab);
                u32 a1 = LD32(ab + 8*208);
                u32 a2 = LD32(ab + 16);
                u32 a3 = LD32(ab + 8*208 + 16);
                const u64* wp = &Wqkvf[(kt*36 + ng2*18 + pass*9)*32 + lane];
                #pragma unroll
                for (int n = 0; n < 9; n++) {
                    u64 w = wp[n*32];
                    mma_bf16(acc[n], a0,a1,a2,a3, (u32)w, (u32)(w>>32));
                }
            }
            #pragma unroll
            for (int n = 0; n < 9; n++) {
                int ntg = ng2*18 + pass*9 + n;
                int c0  = ntg*8 + 2*tig;
                float2 bb = *(const float2*)&Bqkv[c0];
                float sc = (ntg < 12) ? qs : 1.0f;
                float v00 = (acc[n][0]+bb.x)*sc, v01 = (acc[n][1]+bb.y)*sc;
                float v10 = (acc[n][2]+bb.x)*sc, v11 = (acc[n][3]+bb.y)*sc;
                if (ntg < 24) {   // Q | K -> qk rows
                    *(u32*)(smc + OFF_QK + r0*400 + c0*2) = bf2(v00, v01);
                    *(u32*)(smc + OFF_QK + r1*400 + c0*2) = bf2(v10, v11);
                } else {          // V -> transposed vT[ch][tok], ch global 0..95
                    int c = c0 - 192;
                    vt[c*VT_LD + r0]     = __float2bfloat16(v00);
                    vt[(c+1)*VT_LD + r0] = __float2bfloat16(v01);
                    vt[c*VT_LD + r1]     = __float2bfloat16(v10);
                    vt[(c+1)*VT_LD + r1] = __float2bfloat16(v11);
                }
            }
        }
    }
    __syncthreads();

    // ---- Phase 3: S = qK^T + bias, register softmax, probs -> P (bf16) ----
    {
        float sacc[3][4][4];
        #pragma unroll
        for (int h = 0; h < 3; h++)
            #pragma unroll
            for (int j = 0; j < 4; j++)
                sacc[h][j][0]=sacc[h][j][1]=sacc[h][j][2]=sacc[h][j][3]=0.f;

        #pragma unroll
        for (int h = 0; h < 3; h++) {
            #pragma unroll
            for (int kt = 0; kt < 2; kt++) {
                int ab = OFF_QK + r0*400 + h*64 + kt*32 + tig*4;
                u32 a0 = LD32(ab);
                u32 a1 = LD32(ab + 3200);
                u32 a2 = LD32(ab + 16);
                u32 a3 = LD32(ab + 3216);
                #pragma unroll
                for (int j = 0; j < 4; j++) {
                    int tok = ng2*32 + j*8 + gid;
                    int bb  = OFF_QK + tok*400 + 192 + h*64 + kt*32 + tig*4;
                    u32 b0 = LD32(bb);
                    u32 b1 = LD32(bb + 16);
                    mma_bf16(sacc[h][j], a0,a1,a2,a3, b0, b1);
                }
            }
            // add rel-pos bias + per-warp partial max
            const float* bh = biasM + h*4096;
            float m0 = -1e30f, m1 = -1e30f;
            #pragma unroll
            for (int j = 0; j < 4; j++) {
                int cb = ng2*32 + j*8 + 2*tig;
                float2 bb0 = *(const float2*)&bh[r0*64 + cb];
                float2 bb1 = *(const float2*)&bh[r1*64 + cb];
                sacc[h][j][0] += bb0.x; sacc[h][j][1] += bb0.y;
                sacc[h][j][2] += bb1.x; sacc[h][j][3] += bb1.y;
                m0 = fmaxf(m0, fmaxf(sacc[h][j][0], sacc[h][j][1]));
                m1 = fmaxf(m1, fmaxf(sacc[h][j][2], sacc[h][j][3]));
            }
            m0 = fmaxf(m0, __shfl_xor_sync(0xffffffffu, m0, 1));
            m0 = fmaxf(m0, __shfl_xor_sync(0xffffffffu, m0, 2));
            m1 = fmaxf(m1, __shfl_xor_sync(0xffffffffu, m1, 1));
            m1 = fmaxf(m1, __shfl_xor_sync(0xffffffffu, m1, 2));
            if (tig == 0) {
                rmax[(h*64 + r0)*2 + ng2] = m0;
                rmax[(h*64 + r1)*2 + ng2] = m1;
            }
        }
        __syncthreads();

        #pragma unroll
        for (int h = 0; h < 3; h++) {
            float M0 = fmaxf(rmax[(h*64+r0)*2], rmax[(h*64+r0)*2+1]);
            float M1 = fmaxf(rmax[(h*64+r1)*2], rmax[(h*64+r1)*2+1]);
            float s0 = 0.f, s1 = 0.f;
            #pragma unroll
            for (int j = 0; j < 4; j++) {
                sacc[h][j][0] = __expf(sacc[h][j][0] - M0);
                sacc[h][j][1] = __expf(sacc[h][j][1] - M0);
                sacc[h][j][2] = __expf(sacc[h][j][2] - M1);
                sacc[h][j][3] = __expf(sacc[h][j][3] - M1);
                s0 += sacc[h][j][0] + sacc[h][j][1];
                s1 += sacc[h][j][2] + sacc[h][j][3];
            }
            s0 += __shfl_xor_sync(0xffffffffu, s0, 1);
            s0 += __shfl_xor_sync(0xffffffffu, s0, 2);
            s1 += __shfl_xor_sync(0xffffffffu, s1, 1);
            s1 += __shfl_xor_sync(0xffffffffu, s1, 2);
            if (tig == 0) {
                rsum[(h*64 + r0)*2 + ng2] = s0;
                rsum[(h*64 + r1)*2 + ng2] = s1;
            }
        }
        __syncthreads();

        #pragma unroll
        for (int h = 0; h < 3; h++) {
            float i0 = 1.0f / (rsum[(h*64+r0)*2] + rsum[(h*64+r0)*2+1]);
            float i1 = 1.0f / (rsum[(h*64+r1)*2] + rsum[(h*64+r1)*2+1]);
            #pragma unroll
            for (int j = 0; j < 4; j++) {
                int cb = ng2*32 + j*8 + 2*tig;
                *(u32*)(smc + OFF_P + (h*64+r0)*144 + cb*2) =
                    bf2(sacc[h][j][0]*i0, sacc[h][j][1]*i0);
                *(u32*)(smc + OFF_P + (h*64+r1)*144 + cb*2) =
                    bf2(sacc[h][j][2]*i1, sacc[h][j][3]*i1);
            }
        }
    }
    __syncthreads();

    // ---- Phase 4: P@V (bf16 MMA, V transposed) -> ao (xw region) ----
    {
        float acc[6][4];
        #pragma unroll
        for (int j = 0; j < 6; j++)
            acc[j][0]=acc[j][1]=acc[j][2]=acc[j][3]=0.f;
        #pragma unroll
        for (int j = 0; j < 6; j++) {
            int ct = ng2*48 + j*8;      // global output channel base (== global V channel)
            int h  = ct >> 5;           // head for P
            #pragma unroll
            for (int kt = 0; kt < 4; kt++) {
                int ab = OFF_P + (h*64 + r0)*144 + kt*32 + tig*4;
                u32 a0 = LD32(ab);
                u32 a1 = LD32(ab + 8*144);
                u32 a2 = LD32(ab + 16);
                u32 a3 = LD32(ab + 8*144 + 16);
                // FIX (was dc+gid): vt rows are GLOBAL channels -> ct + gid
                int bb = OFF_VT + (ct + gid)*144 + kt*32 + tig*4;
                u32 b0 = LD32(bb);
                u32 b1 = LD32(bb + 16);
                mma_bf16(acc[j], a0,a1,a2,a3, b0, b1);
            }
        }
        #pragma unroll
        for (int j = 0; j < 6; j++) {
            int c0 = ng2*48 + j*8 + 2*tig;
            *(u32*)(smc + OFF_XW + r0*208 + c0*2) = bf2(acc[j][0], acc[j][1]);
            *(u32*)(smc + OFF_XW + r1*208 + c0*2) = bf2(acc[j][2], acc[j][3]);
        }
    }
    __syncthreads();

    // ---- Phase 5: proj (bf16 MMA) + bias; xres += attn ----
    {
        float acc[6][4];
        #pragma unroll
        for (int j = 0; j < 6; j++)
            acc[j][0]=acc[j][1]=acc[j][2]=acc[j][3]=0.f;
        #pragma unroll
        for (int kt = 0; kt < 6; kt++) {
            int ab = OFF_XW + r0*208 + kt*32 + tig*4;
            u32 a0 = LD32(ab);
            u32 a1 = LD32(ab + 8*208);
            u32 a2 = LD32(ab + 16);
            u32 a3 = LD32(ab + 8*208 + 16);
            #pragma unroll
            for (int j = 0; j < 6; j++) {
                u64 w = Wpf[(kt*12 + ng2*6 + j)*32 + lane];
                mma_bf16(acc[j], a0,a1,a2,a3, (u32)w, (u32)(w>>32));
            }
        }
        #pragma unroll
        for (int j = 0; j < 6; j++) {
            int c0 = ng2*48 + j*8 + 2*tig;
            float2 bb  = *(const float2*)&Bp[c0];
            float2 rv0 = *(float2*)&xres[r0*96 + c0];
            float2 rv1 = *(float2*)&xres[r1*96 + c0];
            *(float2*)&xres[r0*96 + c0] = make_float2(acc[j][0]+bb.x+rv0.x, acc[j][1]+bb.y+rv0.y);
            *(float2*)&xres[r1*96 + c0] = make_float2(acc[j][2]+bb.x+rv1.x, acc[j][3]+bb.y+rv1.y);
        }
    }
    __syncthreads();

    // ---- Phase 6: LN2 (xres) -> y (xw region, bf16) ----
    for (int t = warp; t < 64; t += 8) {
        const float* src = &xres[t*96];
        float v0 = src[lane], v1 = src[lane+32], v2 = src[lane+64];
        float s  = v0 + v1 + v2;
        float sq = v0*v0 + v1*v1 + v2*v2;
        #pragma unroll
        for (int o = 16; o; o >>= 1) {
            s  += __shfl_xor_sync(0xffffffffu, s,  o);
            sq += __shfl_xor_sync(0xffffffffu, sq, o);
        }
        float mean = s * (1.0f/96.0f);
        float var  = sq * (1.0f/96.0f) - mean*mean;
        float rstd = rsqrtf(var + 1e-5f);
        xw[t*XW_LD+lane]    = __float2bfloat16((v0-mean)*rstd*g2[lane]    + b2ln[lane]);
        xw[t*XW_LD+lane+32] = __float2bfloat16((v1-mean)*rstd*g2[lane+32] + b2ln[lane+32]);
        xw[t*XW_LD+lane+64] = __float2bfloat16((v2-mean)*rstd*g2[lane+64] + b2ln[lane+64]);
    }
    __syncthreads();

    // ---- Phase 7: MLP GEMM1 (2 passes x 12 n-tiles) + GELU -> hb ----
    for (int pass = 0; pass < 2; pass++) {
        float acc[12][4];
        #pragma unroll
        for (int n = 0; n < 12; n++)
            acc[n][0]=acc[n][1]=acc[n][2]=acc[n][3]=0.f;
        #pragma unroll
        for (int kt = 0; kt < 6; kt++) {
            int ab = OFF_XW + r0*208 + kt*32 + tig*4;
            u32 a0 = LD32(ab);
            u32 a1 = LD32(ab + 8*208);
            u32 a2 = LD32(ab + 16);
            u32 a3 = LD32(ab + 8*208 + 16);
            const u64* wp = &W1f[(kt*48 + ng2*24 + pass*12)*32 + lane];
            #pragma unroll
            for (int n = 0; n < 12; n++) {
                u64 w = wp[n*32];
                mma_bf16(acc[n], a0,a1,a2,a3, (u32)w, (u32)(w>>32));
            }
        }
        #pragma unroll
        for (int n = 0; n < 12; n++) {
            int c0 = (ng2*24 + pass*12 + n)*8 + 2*tig;
            float2 bb = *(const float2*)&B1[c0];
            float u0 = acc[n][0]+bb.x, u1 = acc[n][1]+bb.y;
            float u2 = acc[n][2]+bb.x, u3 = acc[n][3]+bb.y;
            float g0 = 0.5f*u0*(1.0f + erff(u0*0.70710678118654752f));
            float g1v= 0.5f*u1*(1.0f + erff(u1*0.70710678118654752f));
            float g2v= 0.5f*u2*(1.0f + erff(u2*0.70710678118654752f));
            float g3 = 0.5f*u3*(1.0f + erff(u3*0.70710678118654752f));
            *(u32*)(smc + OFF_HB + r0*784 + c0*2) = bf2(g0, g1v);
            *(u32*)(smc + OFF_HB + r1*784 + c0*2) = bf2(g2v, g3);
        }
    }
    __syncthreads();

    // ---- Phase 8: MLP GEMM2 + bias + residual -> out (shifted) ----
    {
        float acc[6][4];
        #pragma unroll
        for (int j = 0; j < 6; j++)
            acc[j][0]=acc[j][1]=acc[j][2]=acc[j][3]=0.f;
        #pragma unroll
        for (int kt = 0; kt < 24; kt++) {
            int ab = OFF_HB + r0*784 + kt*32 + tig*4;
            u32 a0 = LD32(ab);
            u32 a1 = LD32(ab + 8*784);
            u32 a2 = LD32(ab + 16);
            u32 a3 = LD32(ab + 8*784 + 16);
            #pragma unroll
            for (int j = 0; j < 6; j++) {
                u64 w = W2f[(kt*12 + ng2*6 + j)*32 + lane];
                mma_bf16(acc[j], a0,a1,a2,a3, (u32)w, (u32)(w>>32));
            }
        }
        #pragma unroll
        for (int rr = 0; rr < 2; rr++) {
            int t  = (rr ? r1 : r0);
            int td = t >> 4, th = (t >> 2) & 3, tw = t & 3;
            int gd = (wd*4 + td + shift) & 63;
            int gh = (wh*4 + th + shift) & 63;
            int gw = (ww*4 + tw + shift) & 63;
            size_t idx = (size_t)((((b*64 + gd)*64 + gh)*64 + gw)) * 96;
            float* dst = out + idx;
            #pragma unroll
            for (int j = 0; j < 6; j++) {
                int c0 = ng2*48 + j*8 + 2*tig;
                float2 bb = *(const float2*)&B2[c0];
                float2 rv = *(float2*)&xres[t*96 + c0];
                *(float2*)&dst[c0] = make_float2(
                    acc[j][2*rr]   + bb.x + rv.x,
                    acc[j][2*rr+1] + bb.y + rv.y);
            }
        }
    }
}

// ---------------------------------------------------------------------------
extern "C" void kernel_launch(void* const* d_in, const int* in_sizes, int n_in,
                              void* d_out, int out_size)
{
    const float* x      = (const float*)d_in[0];
    const float* qkv_w  = (const float*)d_in[1];
    const float* qkv_b  = (const float*)d_in[2];
    const float* proj_w = (const float*)d_in[3];
    const float* proj_b = (const float*)d_in[4];
    const float* btab   = (const float*)d_in[5];
    const float* ln1g   = (const float*)d_in[6];
    const float* ln1b   = (const float*)d_in[7];
    const float* ln2g   = (const float*)d_in[8];
    const float* ln2b   = (const float*)d_in[9];
    const float* w1     = (const float*)d_in[10];
    const float* b1     = (const float*)d_in[11];
    const float* w2     = (const float*)d_in[12];
    const float* b2     = (const float*)d_in[13];
    float* out = (float*)d_out;

    float* scratch = nullptr;
    u64 *wqkvf = nullptr, *w1f = nullptr, *w2f = nullptr, *wpf = nullptr;
    float* biasm = nullptr;
    cudaGetSymbolAddress((void**)&scratch, g_scratch);
    cudaGetSymbolAddress((void**)&wqkvf,   g_wqkvf);
    cudaGetSymbolAddress((void**)&w1f,     g_w1f);
    cudaGetSymbolAddress((void**)&w2f,     g_w2f);
    cudaGetSymbolAddress((void**)&wpf,     g_wpf);
    cudaGetSymbolAddress((void**)&biasm,   g_bias);

    cudaFuncSetAttribute(block_kernel, cudaFuncAttributeMaxDynamicSharedMemorySize, FSMEM);

    // Prep: bf16 fragment-pack weights + dense bias
    {
        int tq = 2*6*36*32, t1 = 2*6*48*32, t2 = 2*24*12*32, tp = 2*6*12*32;
        pack_kernel<<<(tq+255)/256, 256>>>(qkv_w,  wqkvf, 6, 36, 288, tq);
        pack_kernel<<<(t1+255)/256, 256>>>(w1,     w1f,   6, 48, 384, t1);
        pack_kernel<<<(t2+255)/256, 256>>>(w2,     w2f,  24, 12,  96, t2);
        pack_kernel<<<(tp+255)/256, 256>>>(proj_w, wpf,   6, 12,  96, tp);
        bias_kernel<<<(2*3*64*64+255)/256, 256>>>(btab);
    }

    // ---- block 0 (shift 0): x -> scratch ----
    block_kernel<<<NWIN, 256, FSMEM>>>(x, scratch,
        wqkvf, qkv_b, wpf, proj_b, biasm, ln1g, ln1b,
        ln2g, ln2b, w1f, b1, w2f, b2, 0);

    // ---- block 1 (shift 2): scratch -> out ----
    block_kernel<<<NWIN, 256, FSMEM>>>(scratch, out,
        wqkvf + 6*36*32, qkv_b + 288, wpf + 6*12*32, proj_b + 96,
        biasm + 3*64*64, ln1g + 96, ln1b + 96,
        ln2g + 96, ln2b + 96, w1f + 6*48*32, b1 + 384, w2f + 24*12*32, b2 + 96, 2);
}